// round 1
// baseline (speedup 1.0000x reference)
#include <cuda_runtime.h>
#include <math.h>

#define BSZ  4
#define SEQ  4096
#define DM   1024
#define FF   256
#define ROWS (BSZ*SEQ)            /* 16384 */
#define TAPS 32
#define LN_EPS 1e-5f

// ---------------- scratch (device globals: no alloc allowed) ----------------
__device__ float g_xln   [(size_t)ROWS*DM];
__device__ float g_spec  [(size_t)ROWS*2*FF];
__device__ float g_y     [(size_t)ROWS*2*FF];
__device__ float g_burepr[(size_t)ROWS*DM];
__device__ float g_h     [(size_t)ROWS*DM];
__device__ float g_h2    [(size_t)ROWS*DM];
__device__ float g_w     [2*TAPS*FF];          // [0:TAPS*FF) real taps, then imag
__device__ float g_errpart[16384];

// ---------------- helpers ----------------
__device__ __forceinline__ float block_sum256(float v, float* red) {
    #pragma unroll
    for (int o = 16; o > 0; o >>= 1) v += __shfl_xor_sync(0xffffffffu, v, o);
    int lane = threadIdx.x & 31, w = threadIdx.x >> 5;
    if (lane == 0) red[w] = v;
    __syncthreads();
    if (w == 0) {
        float r = (lane < 8) ? red[lane] : 0.f;
        #pragma unroll
        for (int o = 4; o > 0; o >>= 1) r += __shfl_xor_sync(0xffffffffu, r, o);
        if (lane == 0) red[0] = r;
    }
    __syncthreads();
    float out = red[0];
    __syncthreads();
    return out;
}

// ---------------- FIR tap precompute ----------------
__global__ void prep_kernel(const float* __restrict__ log_decay,
                            const float* __restrict__ freq) {
    int f = threadIdx.x;                  // 256 threads = FF
    float decay = 1.f / (1.f + expf(-log_decay[f]));
    float omega = tanhf(freq[f]) * 0.1f;
    float cr = cosf(omega), ci = sinf(omega);
    float Ar = decay * cr, Ai = decay * ci;
    float pr = 1.f, pi = 0.f;             // A^0
    #pragma unroll 1
    for (int t = 0; t < TAPS; t++) {
        g_w[t*FF + f]           = pr*cr - pi*ci;   // (A^t * rot).real
        g_w[TAPS*FF + t*FF + f] = pr*ci + pi*cr;   // (A^t * rot).imag
        float nr = pr*Ar - pi*Ai;
        float ni = pr*Ai + pi*Ar;
        pr = nr; pi = ni;
    }
}

// ---------------- LayerNorm over D=1024, 1 block per row ----------------
__global__ void ln_kernel(const float* __restrict__ x, const float* __restrict__ g,
                          const float* __restrict__ b, float* __restrict__ out) {
    __shared__ float red[8];
    int row = blockIdx.x, tid = threadIdx.x;
    const float4* xr = (const float4*)(x + (size_t)row*DM);
    float4 v = xr[tid];
    float mu = block_sum256(v.x + v.y + v.z + v.w, red) * (1.f/DM);
    float dx = v.x - mu, dy = v.y - mu, dz = v.z - mu, dw = v.w - mu;
    float var = block_sum256(dx*dx + dy*dy + dz*dz + dw*dw, red) * (1.f/DM);
    float rs = rsqrtf(var + LN_EPS);
    float4 gv = ((const float4*)g)[tid];
    float4 bv = ((const float4*)b)[tid];
    float4 o = make_float4(dx*rs*gv.x + bv.x, dy*rs*gv.y + bv.y,
                           dz*rs*gv.z + bv.z, dw*rs*gv.w + bv.w);
    ((float4*)(out + (size_t)row*DM))[tid] = o;
}

// ---------------- TN GEMM: C[M,N] = A[M,K] * B[N,K]^T (+bias)(+gelu) --------
// 128x128x16 tile, 256 threads, 8x8 microtile.
template<bool BIAS, bool GELU>
__global__ void __launch_bounds__(256, 2)
gemm_tn(const float* __restrict__ A, const float* __restrict__ Bm,
        const float* __restrict__ bias, float* __restrict__ C,
        int M, int N, int K) {
    __shared__ float As[16][132];
    __shared__ float Bs[16][132];
    const int m0 = blockIdx.y * 128;
    const int n0 = blockIdx.x * 128;
    const int tid = threadIdx.x;
    const int tx = tid & 15, ty = tid >> 4;

    float acc[8][8];
    #pragma unroll
    for (int i = 0; i < 8; i++)
        #pragma unroll
        for (int j = 0; j < 8; j++) acc[i][j] = 0.f;

    for (int kt = 0; kt < K; kt += 16) {
        #pragma unroll
        for (int l = 0; l < 2; l++) {
            int i  = tid + l*256;           // 512 float4 loads per operand
            int r  = i >> 2, c4 = i & 3;
            float4 va = *(const float4*)(A  + (size_t)(m0 + r)*K + kt + c4*4);
            As[c4*4+0][r] = va.x; As[c4*4+1][r] = va.y;
            As[c4*4+2][r] = va.z; As[c4*4+3][r] = va.w;
            float4 vb = *(const float4*)(Bm + (size_t)(n0 + r)*K + kt + c4*4);
            Bs[c4*4+0][r] = vb.x; Bs[c4*4+1][r] = vb.y;
            Bs[c4*4+2][r] = vb.z; Bs[c4*4+3][r] = vb.w;
        }
        __syncthreads();
        #pragma unroll
        for (int k = 0; k < 16; k++) {
            float af[8], bf[8];
            *(float4*)&af[0] = *(const float4*)&As[k][ty*8];
            *(float4*)&af[4] = *(const float4*)&As[k][ty*8 + 4];
            *(float4*)&bf[0] = *(const float4*)&Bs[k][tx*8];
            *(float4*)&bf[4] = *(const float4*)&Bs[k][tx*8 + 4];
            #pragma unroll
            for (int i = 0; i < 8; i++)
                #pragma unroll
                for (int j = 0; j < 8; j++)
                    acc[i][j] += af[i] * bf[j];
        }
        __syncthreads();
    }

    #pragma unroll
    for (int i = 0; i < 8; i++) {
        int m = m0 + ty*8 + i;
        float vv[8];
        #pragma unroll
        for (int j = 0; j < 8; j++) {
            float v = acc[i][j];
            if (BIAS) v += bias[n0 + tx*8 + j];
            if (GELU) v = 0.5f * v * (1.f + erff(v * 0.70710678118654752f));
            vv[j] = v;
        }
        float* crow = C + (size_t)m*N + n0 + tx*8;
        *(float4*)(crow)     = make_float4(vv[0], vv[1], vv[2], vv[3]);
        *(float4*)(crow + 4) = make_float4(vv[4], vv[5], vv[6], vv[7]);
    }
}

// ---------------- 32-tap complex causal FIR along S ----------------
// u, y: [ROWS, 2F] with real in [0,F), imag in [F,2F). Tile: 64 t x 32 f.
__global__ void conv_kernel(const float* __restrict__ u, float* __restrict__ y) {
    __shared__ float sur[95*32], sui[95*32];
    __shared__ float swr[TAPS*32], swi[TAPS*32];
    const int f0 = blockIdx.x * 32;
    const int t0 = blockIdx.y * 64;
    const int b  = blockIdx.z;
    const int tid = threadIdx.x;

    for (int i = tid; i < 95*32; i += 256) {
        int tt = i >> 5, fl = i & 31;
        int tg = t0 - 31 + tt;
        float vr = 0.f, vi = 0.f;
        if (tg >= 0) {
            size_t base = ((size_t)(b*SEQ + tg))*(2*FF) + f0 + fl;
            vr = u[base]; vi = u[base + FF];
        }
        sur[i] = vr; sui[i] = vi;
    }
    for (int i = tid; i < TAPS*32; i += 256) {
        int tt = i >> 5, fl = i & 31;
        swr[i] = g_w[tt*FF + f0 + fl];
        swi[i] = g_w[TAPS*FF + tt*FF + f0 + fl];
    }
    __syncthreads();

    const int fl = tid & 31, tr = tid >> 5;
    #pragma unroll
    for (int j = 0; j < 8; j++) {
        int tl = tr*8 + j;
        float ar = 0.f, ai = 0.f;
        #pragma unroll
        for (int t = 0; t < TAPS; t++) {
            int idx = (31 + tl - t)*32 + fl;
            float ur = sur[idx], ui = sui[idx];
            float wr = swr[t*32 + fl], wi = swi[t*32 + fl];
            ar += ur*wr - ui*wi;
            ai += ur*wi + ui*wr;
        }
        size_t ob = ((size_t)(b*SEQ + t0 + tl))*(2*FF) + f0 + fl;
        y[ob] = ar; y[ob + FF] = ai;
    }
}

// ---------------- error / corrected + partial sums ----------------
__global__ void err_kernel(const float* __restrict__ bu, const float* __restrict__ td,
                           const float* __restrict__ ew, float* __restrict__ corr) {
    __shared__ float red[8];
    size_t i = ((size_t)blockIdx.x*256 + threadIdx.x)*4;
    float sw = 1.f / (1.f + expf(-ew[0]));
    float4 r = *(const float4*)(bu + i);
    float4 t = *(const float4*)(td + i);
    float ex = fminf(fmaxf(r.x - t.x, -1.f), 1.f);
    float ey = fminf(fmaxf(r.y - t.y, -1.f), 1.f);
    float ez = fminf(fmaxf(r.z - t.z, -1.f), 1.f);
    float e2 = fminf(fmaxf(r.w - t.w, -1.f), 1.f);
    *(float4*)(corr + i) = make_float4(r.x - sw*ex, r.y - sw*ey, r.z - sw*ez, r.w - sw*e2);
    float s = block_sum256(ex*ex + ey*ey + ez*ez + e2*e2, red);
    if (threadIdx.x == 0) g_errpart[blockIdx.x] = s;
}

__global__ void fin_kernel(float* __restrict__ out_scalar) {
    __shared__ float red[8];
    float s = 0.f;
    for (int i = threadIdx.x; i < 16384; i += 256) s += g_errpart[i];
    s = block_sum256(s, red);
    if (threadIdx.x == 0) {
        float pe = s / (float)((size_t)ROWS * DM);
        out_scalar[0] = fminf(fmaxf(pe, 0.f), 1.f);
    }
}

// ---------------- launch ----------------
extern "C" void kernel_launch(void* const* d_in, const int* in_sizes, int n_in,
                              void* d_out, int out_size) {
    const float* bu    = (const float*)d_in[0];
    const float* td    = (const float*)d_in[1];
    const float* Wspec = (const float*)d_in[2];
    const float* ldec  = (const float*)d_in[3];
    const float* freq  = (const float*)d_in[4];
    const float* Wfrom = (const float*)d_in[5];
    const float* l1g   = (const float*)d_in[6];
    const float* l1b   = (const float*)d_in[7];
    const float* W1    = (const float*)d_in[8];
    const float* b1    = (const float*)d_in[9];
    const float* W2    = (const float*)d_in[10];
    const float* b2    = (const float*)d_in[11];
    const float* l2g   = (const float*)d_in[12];
    const float* l2b   = (const float*)d_in[13];
    const float* ew    = (const float*)d_in[14];

    float* out       = (float*)d_out;
    float* corrected = out;                             // [ROWS*DM]
    float* nextpred  = out + (size_t)ROWS*DM;           // [ROWS*DM]
    float* pe        = out + 2*(size_t)ROWS*DM;         // [1]

    float *xln, *spec, *yb, *burepr, *h, *h2;
    cudaGetSymbolAddress((void**)&xln,    g_xln);
    cudaGetSymbolAddress((void**)&spec,   g_spec);
    cudaGetSymbolAddress((void**)&yb,     g_y);
    cudaGetSymbolAddress((void**)&burepr, g_burepr);
    cudaGetSymbolAddress((void**)&h,      g_h);
    cudaGetSymbolAddress((void**)&h2,     g_h2);

    prep_kernel<<<1, 256>>>(ldec, freq);
    ln_kernel<<<ROWS, 256>>>(bu, l1g, l1b, xln);
    gemm_tn<false,false><<<dim3((2*FF)/128, ROWS/128), 256>>>(xln, Wspec, nullptr, spec, ROWS, 2*FF, DM);
    conv_kernel<<<dim3(FF/32, SEQ/64, BSZ), 256>>>(spec, yb);
    gemm_tn<false,false><<<dim3(DM/128, ROWS/128), 256>>>(yb, Wfrom, nullptr, burepr, ROWS, DM, 2*FF);
    err_kernel<<<16384, 256>>>(burepr, td, ew, corrected);
    fin_kernel<<<1, 256>>>(pe);
    gemm_tn<true,true ><<<dim3(DM/128, ROWS/128), 256>>>(corrected, W1, b1, h, ROWS, DM, DM);
    gemm_tn<true,false><<<dim3(DM/128, ROWS/128), 256>>>(h, W2, b2, h2, ROWS, DM, DM);
    ln_kernel<<<ROWS, 256>>>(h2, l2g, l2b, nextpred);
}

// round 3
// speedup vs baseline: 1.4573x; 1.4573x over previous
#include <cuda_runtime.h>
#include <cuda_bf16.h>
#include <math.h>
#include <stdint.h>

#define BSZ  4
#define SEQ  4096
#define DM   1024
#define FF   256
#define ROWS (BSZ*SEQ)            /* 16384 */
#define TAPS 32
#define LN_EPS 1e-5f

// ---------------- scratch (device globals: no alloc allowed) ----------------
__device__ float g_spec  [(size_t)ROWS*2*FF];   // fp32 GEMM1 out (conv input)
__device__ float g_burepr[(size_t)ROWS*DM];     // fp32 GEMM2 out
__device__ float g_h2    [(size_t)ROWS*DM];     // fp32 GEMM4 out
__device__ __nv_bfloat16 g_xh[(size_t)ROWS*DM],  g_xl[(size_t)ROWS*DM];
__device__ __nv_bfloat16 g_yh[(size_t)ROWS*2*FF],g_yl[(size_t)ROWS*2*FF];
__device__ __nv_bfloat16 g_ch[(size_t)ROWS*DM],  g_cl[(size_t)ROWS*DM];
__device__ __nv_bfloat16 g_hh[(size_t)ROWS*DM],  g_hl[(size_t)ROWS*DM];
__device__ __nv_bfloat16 g_wsh[2*FF*DM], g_wsl[2*FF*DM];
__device__ __nv_bfloat16 g_wfh[DM*2*FF], g_wfl[DM*2*FF];
__device__ __nv_bfloat16 g_w1h[DM*DM],   g_w1l[DM*DM];
__device__ __nv_bfloat16 g_w2h[DM*DM],   g_w2l[DM*DM];
__device__ float g_w[2*TAPS*FF];
__device__ float g_errpart[16384];

// ---------------- PTX helpers ----------------
__device__ __forceinline__ uint32_t smem_u32(const void* p){
    uint32_t a; asm("{ .reg .u64 t; cvta.to.shared.u64 t, %1; cvt.u32.u64 %0, t; }":"=r"(a):"l"(p)); return a;
}
#define CPA16(dst,src) asm volatile("cp.async.cg.shared.global [%0],[%1],16;"::"r"(dst),"l"(src))
#define CPA_COMMIT()   asm volatile("cp.async.commit_group;":::"memory")
#define CPA_WAIT1()    asm volatile("cp.async.wait_group 1;":::"memory")
#define CPA_WAIT0()    asm volatile("cp.async.wait_group 0;":::"memory")

#define LDSM_X4(r0,r1,r2,r3,addr) \
    asm volatile("ldmatrix.sync.aligned.m8n8.x4.shared.b16 {%0,%1,%2,%3},[%4];" \
        : "=r"(r0),"=r"(r1),"=r"(r2),"=r"(r3) : "r"(addr))

#define MMA16816(d,a,b) \
    asm volatile("mma.sync.aligned.m16n8k16.row.col.f32.bf16.bf16.f32 " \
        "{%0,%1,%2,%3},{%4,%5,%6,%7},{%8,%9},{%0,%1,%2,%3};" \
        : "+f"((d)[0]),"+f"((d)[1]),"+f"((d)[2]),"+f"((d)[3]) \
        : "r"((a)[0]),"r"((a)[1]),"r"((a)[2]),"r"((a)[3]),"r"((b)[0]),"r"((b)[1]))

__device__ __forceinline__ void split2(float v, __nv_bfloat16& h, __nv_bfloat16& l){
    h = __float2bfloat16(v);
    l = __float2bfloat16(v - __bfloat162float(h));
}

// ---------------- block reduce ----------------
__device__ __forceinline__ float block_sum256(float v, float* red) {
    #pragma unroll
    for (int o = 16; o > 0; o >>= 1) v += __shfl_xor_sync(0xffffffffu, v, o);
    int lane = threadIdx.x & 31, w = threadIdx.x >> 5;
    if (lane == 0) red[w] = v;
    __syncthreads();
    if (w == 0) {
        float r = (lane < 8) ? red[lane] : 0.f;
        #pragma unroll
        for (int o = 4; o > 0; o >>= 1) r += __shfl_xor_sync(0xffffffffu, r, o);
        if (lane == 0) red[0] = r;
    }
    __syncthreads();
    float out = red[0];
    __syncthreads();
    return out;
}

// ---------------- FIR tap precompute ----------------
__global__ void prep_kernel(const float* __restrict__ log_decay,
                            const float* __restrict__ freq) {
    int f = threadIdx.x;
    float decay = 1.f / (1.f + expf(-log_decay[f]));
    float omega = tanhf(freq[f]) * 0.1f;
    float cr = cosf(omega), ci = sinf(omega);
    float Ar = decay * cr, Ai = decay * ci;
    float pr = 1.f, pi = 0.f;
    #pragma unroll 1
    for (int t = 0; t < TAPS; t++) {
        g_w[t*FF + f]           = pr*cr - pi*ci;
        g_w[TAPS*FF + t*FF + f] = pr*ci + pi*cr;
        float nr = pr*Ar - pi*Ai, ni = pr*Ai + pi*Ar;
        pr = nr; pi = ni;
    }
}

// ---------------- weight split ----------------
__global__ void wsplit_kernel(const float* __restrict__ w,
                              __nv_bfloat16* __restrict__ h, __nv_bfloat16* __restrict__ l, int n){
    int i = blockIdx.x*256 + threadIdx.x;
    if (i < n) { __nv_bfloat16 hi, lo; split2(w[i], hi, lo); h[i] = hi; l[i] = lo; }
}

// ---------------- LayerNorm over D=1024 ----------------
template<bool SPLIT>
__global__ void ln_kernel(const float* __restrict__ x, const float* __restrict__ g,
                          const float* __restrict__ b, float* __restrict__ outf,
                          __nv_bfloat16* __restrict__ oh, __nv_bfloat16* __restrict__ ol) {
    __shared__ float red[8];
    int row = blockIdx.x, tid = threadIdx.x;
    float4 v = ((const float4*)(x + (size_t)row*DM))[tid];
    float mu = block_sum256(v.x + v.y + v.z + v.w, red) * (1.f/DM);
    float dx = v.x - mu, dy = v.y - mu, dz = v.z - mu, dw = v.w - mu;
    float var = block_sum256(dx*dx + dy*dy + dz*dz + dw*dw, red) * (1.f/DM);
    float rs = rsqrtf(var + LN_EPS);
    float4 gv = ((const float4*)g)[tid];
    float4 bv = ((const float4*)b)[tid];
    float o0 = dx*rs*gv.x + bv.x, o1 = dy*rs*gv.y + bv.y;
    float o2 = dz*rs*gv.z + bv.z, o3 = dw*rs*gv.w + bv.w;
    if (SPLIT) {
        __nv_bfloat16 h0,l0,h1,l1,h2,l2,h3,l3;
        split2(o0,h0,l0); split2(o1,h1,l1); split2(o2,h2,l2); split2(o3,h3,l3);
        size_t base = (size_t)row*DM + tid*4;
        ((__nv_bfloat162*)(oh+base))[0] = __halves2bfloat162(h0,h1);
        ((__nv_bfloat162*)(oh+base))[1] = __halves2bfloat162(h2,h3);
        ((__nv_bfloat162*)(ol+base))[0] = __halves2bfloat162(l0,l1);
        ((__nv_bfloat162*)(ol+base))[1] = __halves2bfloat162(l2,l3);
    } else {
        ((float4*)(outf + (size_t)row*DM))[tid] = make_float4(o0,o1,o2,o3);
    }
}

// ---------------- HMMA bf16x3 GEMM: C[M,N] = A[M,K] * B[N,K]^T -------------
// tile 128x128x32, 8 warps (warp tile 64x32), 2-stage cp.async.
// smem rows padded to 80B: bank-conflict-free for cp.async writes and ldmatrix.
#define ROWB 80u
#define TILEB (128u*ROWB)      /* 10240 */
#define STAGE (4u*TILEB)       /* 40960 */

template<bool BIAS, bool GELU, bool SPLIT>
__global__ void __launch_bounds__(256, 2) gemm_mma(
    const __nv_bfloat16* __restrict__ Ah, const __nv_bfloat16* __restrict__ Al,
    const __nv_bfloat16* __restrict__ Bh, const __nv_bfloat16* __restrict__ Bl,
    const float* __restrict__ bias,
    float* __restrict__ Cf, __nv_bfloat16* __restrict__ Ch, __nv_bfloat16* __restrict__ Cl,
    int M, int N, int K)
{
    extern __shared__ char dsm[];
    const uint32_t sb = smem_u32(dsm);
    const uint32_t OAH = 0, OAL = TILEB, OBH = 2*TILEB, OBL = 3*TILEB;

    const int m0 = blockIdx.y * 128, n0 = blockIdx.x * 128;
    const int tid = threadIdx.x, lane = tid & 31, wid = tid >> 5;
    const int wm0 = (wid & 1) * 64, wn0 = (wid >> 1) * 32;
    const int NC = K >> 5;

    float acc[4][4][4];
    #pragma unroll
    for (int i = 0; i < 4; i++)
        #pragma unroll
        for (int j = 0; j < 4; j++)
            #pragma unroll
            for (int r = 0; r < 4; r++) acc[i][j][r] = 0.f;

    // cp.async roles: idx = tid + l*256 -> row = idx>>2, granule g = idx&3
    const int lr = tid >> 2, lg = tid & 3;

    auto load_stage = [&](int c){
        uint32_t s0 = sb + (uint32_t)(c & 1)*STAGE;
        size_t ko = (size_t)c * 32;
        #pragma unroll
        for (int l = 0; l < 2; l++) {
            int r = lr + l*64;
            uint32_t d = s0 + (uint32_t)r*ROWB + (uint32_t)lg*16u;
            const char* sa = (const char*)(Ah + (size_t)(m0 + r)*K + ko + lg*8);
            const char* sal= (const char*)(Al + (size_t)(m0 + r)*K + ko + lg*8);
            const char* sbh= (const char*)(Bh + (size_t)(n0 + r)*K + ko + lg*8);
            const char* sbl= (const char*)(Bl + (size_t)(n0 + r)*K + ko + lg*8);
            CPA16(d + OAH, sa);
            CPA16(d + OAL, sal);
            CPA16(d + OBH, sbh);
            CPA16(d + OBL, sbl);
        }
        CPA_COMMIT();
    };

    // ldmatrix addresses (byte offsets within a tile)
    // A (x4, m16k16): rows wm0 + mi*16 + (lane&15), kg = lane>>4
    const uint32_t a_row = (uint32_t)(wm0 + (lane & 15));
    const uint32_t a_kg  = (uint32_t)(lane >> 4);
    // B (x4, two n8 tiles): sel = lane>>3; nrow = wn0 + (nj + (sel>>1))*8 + (lane&7); kg = sel&1
    const uint32_t b_sel = (uint32_t)(lane >> 3);
    const uint32_t b_row = (uint32_t)(wn0 + ((b_sel >> 1) << 3) + (lane & 7));
    const uint32_t b_kg  = b_sel & 1u;

    load_stage(0);
    for (int c = 0; c < NC; c++) {
        if (c + 1 < NC) { load_stage(c + 1); CPA_WAIT1(); }
        else           { CPA_WAIT0(); }
        __syncthreads();
        uint32_t s0 = sb + (uint32_t)(c & 1)*STAGE;

        #pragma unroll
        for (int s = 0; s < 2; s++) {       // two k16 steps per chunk
            uint32_t ah[4][4], al[4][4], bh[4][2], bl[4][2];
            #pragma unroll
            for (int mi = 0; mi < 4; mi++) {
                uint32_t ad = s0 + (a_row + mi*16u)*ROWB + ((uint32_t)s*2u + a_kg)*16u;
                LDSM_X4(ah[mi][0], ah[mi][1], ah[mi][2], ah[mi][3], ad + OAH);
                LDSM_X4(al[mi][0], al[mi][1], al[mi][2], al[mi][3], ad + OAL);
            }
            #pragma unroll
            for (int nj = 0; nj < 4; nj += 2) {
                uint32_t bd = s0 + (b_row + (uint32_t)nj*8u)*ROWB + ((uint32_t)s*2u + b_kg)*16u;
                LDSM_X4(bh[nj][0], bh[nj][1], bh[nj+1][0], bh[nj+1][1], bd + OBH);
                LDSM_X4(bl[nj][0], bl[nj][1], bl[nj+1][0], bl[nj+1][1], bd + OBL);
            }
            #pragma unroll
            for (int mi = 0; mi < 4; mi++)
                #pragma unroll
                for (int ni = 0; ni < 4; ni++) {
                    MMA16816(acc[mi][ni], ah[mi], bh[ni]);
                    MMA16816(acc[mi][ni], ah[mi], bl[ni]);
                    MMA16816(acc[mi][ni], al[mi], bh[ni]);
                }
        }
        __syncthreads();
    }

    // epilogue: thread holds c[m][n]; m = m0+wm0+mi*16+(lane>>2)+8*(reg>=2),
    // n = n0+wn0+ni*8+(lane&3)*2+(reg&1)
    const int er = lane >> 2, ec = (lane & 3) * 2;
    #pragma unroll
    for (int mi = 0; mi < 4; mi++) {
        #pragma unroll
        for (int half = 0; half < 2; half++) {
            int m = m0 + wm0 + mi*16 + er + half*8;
            #pragma unroll
            for (int ni = 0; ni < 4; ni++) {
                int n = n0 + wn0 + ni*8 + ec;
                float v0 = acc[mi][ni][half*2 + 0];
                float v1 = acc[mi][ni][half*2 + 1];
                if (BIAS) { v0 += __ldg(&bias[n]); v1 += __ldg(&bias[n+1]); }
                if (GELU) {
                    v0 = 0.5f * v0 * (1.f + erff(v0 * 0.70710678118654752f));
                    v1 = 0.5f * v1 * (1.f + erff(v1 * 0.70710678118654752f));
                }
                if (SPLIT) {
                    __nv_bfloat16 h0,l0,h1,l1;
                    split2(v0,h0,l0); split2(v1,h1,l1);
                    *(__nv_bfloat162*)(Ch + (size_t)m*N + n) = __halves2bfloat162(h0,h1);
                    *(__nv_bfloat162*)(Cl + (size_t)m*N + n) = __halves2bfloat162(l0,l1);
                } else {
                    *(float2*)(Cf + (size_t)m*N + n) = make_float2(v0, v1);
                }
            }
        }
    }
}

// ---------------- 32-tap complex causal FIR along S (bf16-split output) ----
__global__ void conv_kernel(const float* __restrict__ u,
                            __nv_bfloat16* __restrict__ yh, __nv_bfloat16* __restrict__ yl) {
    __shared__ float sur[95*32], sui[95*32];
    __shared__ float swr[TAPS*32], swi[TAPS*32];
    const int f0 = blockIdx.x * 32;
    const int t0 = blockIdx.y * 64;
    const int b  = blockIdx.z;
    const int tid = threadIdx.x;

    for (int i = tid; i < 95*32; i += 256) {
        int tt = i >> 5, fl = i & 31;
        int tg = t0 - 31 + tt;
        float vr = 0.f, vi = 0.f;
        if (tg >= 0) {
            size_t base = ((size_t)(b*SEQ + tg))*(2*FF) + f0 + fl;
            vr = u[base]; vi = u[base + FF];
        }
        sur[i] = vr; sui[i] = vi;
    }
    for (int i = tid; i < TAPS*32; i += 256) {
        int tt = i >> 5, fl = i & 31;
        swr[i] = g_w[tt*FF + f0 + fl];
        swi[i] = g_w[TAPS*FF + tt*FF + f0 + fl];
    }
    __syncthreads();

    const int fl = tid & 31, tr = tid >> 5;
    #pragma unroll
    for (int j = 0; j < 8; j++) {
        int tl = tr*8 + j;
        float ar = 0.f, ai = 0.f;
        #pragma unroll
        for (int t = 0; t < TAPS; t++) {
            int idx = (31 + tl - t)*32 + fl;
            float ur = sur[idx], ui = sui[idx];
            float wr = swr[t*32 + fl], wi = swi[t*32 + fl];
            ar += ur*wr - ui*wi;
            ai += ur*wi + ui*wr;
        }
        size_t ob = ((size_t)(b*SEQ + t0 + tl))*(2*FF) + f0 + fl;
        __nv_bfloat16 h, l;
        split2(ar, h, l); yh[ob] = h;      yl[ob] = l;
        split2(ai, h, l); yh[ob + FF] = h; yl[ob + FF] = l;
    }
}

// ---------------- error / corrected (+bf16 split) + partial sums -----------
__global__ void err_kernel(const float* __restrict__ bu, const float* __restrict__ td,
                           const float* __restrict__ ew, float* __restrict__ corr,
                           __nv_bfloat16* __restrict__ ch, __nv_bfloat16* __restrict__ cl) {
    __shared__ float red[8];
    size_t i = ((size_t)blockIdx.x*256 + threadIdx.x)*4;
    float sw = 1.f / (1.f + expf(-ew[0]));
    float4 r = *(const float4*)(bu + i);
    float4 t = *(const float4*)(td + i);
    float ex = fminf(fmaxf(r.x - t.x, -1.f), 1.f);
    float ey = fminf(fmaxf(r.y - t.y, -1.f), 1.f);
    float ez = fminf(fmaxf(r.z - t.z, -1.f), 1.f);
    float e2 = fminf(fmaxf(r.w - t.w, -1.f), 1.f);
    float c0 = r.x - sw*ex, c1 = r.y - sw*ey, c2 = r.z - sw*ez, c3 = r.w - sw*e2;
    *(float4*)(corr + i) = make_float4(c0, c1, c2, c3);
    __nv_bfloat16 h0,l0,h1,l1,h2,l2,h3,l3;
    split2(c0,h0,l0); split2(c1,h1,l1); split2(c2,h2,l2); split2(c3,h3,l3);
    ((__nv_bfloat162*)(ch+i))[0] = __halves2bfloat162(h0,h1);
    ((__nv_bfloat162*)(ch+i))[1] = __halves2bfloat162(h2,h3);
    ((__nv_bfloat162*)(cl+i))[0] = __halves2bfloat162(l0,l1);
    ((__nv_bfloat162*)(cl+i))[1] = __halves2bfloat162(l2,l3);
    float s = block_sum256(ex*ex + ey*ey + ez*ez + e2*e2, red);
    if (threadIdx.x == 0) g_errpart[blockIdx.x] = s;
}

__global__ void fin_kernel(float* __restrict__ out_scalar) {
    __shared__ float red[8];
    float s = 0.f;
    for (int i = threadIdx.x; i < 16384; i += 256) s += g_errpart[i];
    s = block_sum256(s, red);
    if (threadIdx.x == 0) {
        float pe = s / (float)((size_t)ROWS * DM);
        out_scalar[0] = fminf(fmaxf(pe, 0.f), 1.f);
    }
}

// ---------------- launch ----------------
extern "C" void kernel_launch(void* const* d_in, const int* in_sizes, int n_in,
                              void* d_out, int out_size) {
    const float* bu    = (const float*)d_in[0];
    const float* td    = (const float*)d_in[1];
    const float* Wspec = (const float*)d_in[2];
    const float* ldec  = (const float*)d_in[3];
    const float* freq  = (const float*)d_in[4];
    const float* Wfrom = (const float*)d_in[5];
    const float* l1g   = (const float*)d_in[6];
    const float* l1b   = (const float*)d_in[7];
    const float* W1    = (const float*)d_in[8];
    const float* b1    = (const float*)d_in[9];
    const float* W2    = (const float*)d_in[10];
    const float* b2    = (const float*)d_in[11];
    const float* l2g   = (const float*)d_in[12];
    const float* l2b   = (const float*)d_in[13];
    const float* ew    = (const float*)d_in[14];

    float* out       = (float*)d_out;
    float* corrected = out;
    float* nextpred  = out + (size_t)ROWS*DM;
    float* pe        = out + 2*(size_t)ROWS*DM;

    float *spec, *burepr, *h2;
    __nv_bfloat16 *xh,*xl,*yh,*yl,*ch,*cl,*hh,*hl;
    __nv_bfloat16 *wsh,*wsl,*wfh,*wfl,*w1h,*w1l,*w2h,*w2l;
    cudaGetSymbolAddress((void**)&spec,   g_spec);
    cudaGetSymbolAddress((void**)&burepr, g_burepr);
    cudaGetSymbolAddress((void**)&h2,     g_h2);
    cudaGetSymbolAddress((void**)&xh, g_xh); cudaGetSymbolAddress((void**)&xl, g_xl);
    cudaGetSymbolAddress((void**)&yh, g_yh); cudaGetSymbolAddress((void**)&yl, g_yl);
    cudaGetSymbolAddress((void**)&ch, g_ch); cudaGetSymbolAddress((void**)&cl, g_cl);
    cudaGetSymbolAddress((void**)&hh, g_hh); cudaGetSymbolAddress((void**)&hl, g_hl);
    cudaGetSymbolAddress((void**)&wsh, g_wsh); cudaGetSymbolAddress((void**)&wsl, g_wsl);
    cudaGetSymbolAddress((void**)&wfh, g_wfh); cudaGetSymbolAddress((void**)&wfl, g_wfl);
    cudaGetSymbolAddress((void**)&w1h, g_w1h); cudaGetSymbolAddress((void**)&w1l, g_w1l);
    cudaGetSymbolAddress((void**)&w2h, g_w2h); cudaGetSymbolAddress((void**)&w2l, g_w2l);

    const int SMEM_BYTES = 2 * (int)STAGE;   // 81920
    cudaFuncSetAttribute(gemm_mma<false,false,false>, cudaFuncAttributeMaxDynamicSharedMemorySize, SMEM_BYTES);
    cudaFuncSetAttribute(gemm_mma<true ,true ,true >, cudaFuncAttributeMaxDynamicSharedMemorySize, SMEM_BYTES);
    cudaFuncSetAttribute(gemm_mma<true ,false,false>, cudaFuncAttributeMaxDynamicSharedMemorySize, SMEM_BYTES);

    prep_kernel<<<1, 256>>>(ldec, freq);
    wsplit_kernel<<<(2*FF*DM+255)/256, 256>>>(Wspec, wsh, wsl, 2*FF*DM);
    wsplit_kernel<<<(DM*2*FF+255)/256, 256>>>(Wfrom, wfh, wfl, DM*2*FF);
    wsplit_kernel<<<(DM*DM+255)/256, 256>>>(W1, w1h, w1l, DM*DM);
    wsplit_kernel<<<(DM*DM+255)/256, 256>>>(W2, w2h, w2l, DM*DM);

    ln_kernel<true><<<ROWS, 256>>>(bu, l1g, l1b, nullptr, xh, xl);

    gemm_mma<false,false,false><<<dim3((2*FF)/128, ROWS/128), 256, SMEM_BYTES>>>(
        xh, xl, wsh, wsl, nullptr, spec, nullptr, nullptr, ROWS, 2*FF, DM);

    conv_kernel<<<dim3(FF/32, SEQ/64, BSZ), 256>>>(spec, yh, yl);

    gemm_mma<false,false,false><<<dim3(DM/128, ROWS/128), 256, SMEM_BYTES>>>(
        yh, yl, wfh, wfl, nullptr, burepr, nullptr, nullptr, ROWS, DM, 2*FF);

    err_kernel<<<16384, 256>>>(burepr, td, ew, corrected, ch, cl);
    fin_kernel<<<1, 256>>>(pe);

    gemm_mma<true,true,true><<<dim3(DM/128, ROWS/128), 256, SMEM_BYTES>>>(
        ch, cl, w1h, w1l, b1, nullptr, hh, hl, ROWS, DM, DM);

    gemm_mma<true,false,false><<<dim3(DM/128, ROWS/128), 256, SMEM_BYTES>>>(
        hh, hl, w2h, w2l, b2, h2, nullptr, nullptr, ROWS, DM, DM);

    ln_kernel<false><<<ROWS, 256>>>(h2, l2g, l2b, nextpred, nullptr, nullptr);
}

// round 4
// speedup vs baseline: 1.8470x; 1.2675x over previous
#include <cuda_runtime.h>
#include <cuda_fp16.h>
#include <math.h>
#include <stdint.h>

#define BSZ  4
#define SEQ  4096
#define DM   1024
#define FF   256
#define ROWS (BSZ*SEQ)            /* 16384 */
#define TAPS 32
#define LN_EPS 1e-5f
#define LO_S   2048.0f
#define LO_INV 4.8828125e-4f

// ---------------- scratch (device globals: no alloc allowed) ----------------
__device__ float g_spec  [(size_t)ROWS*2*FF];   // fp32 GEMM1 out (conv input)
__device__ float g_h2    [(size_t)ROWS*DM];     // fp32 GEMM4 out
__device__ __half g_xh[(size_t)ROWS*DM],  g_xl[(size_t)ROWS*DM];
__device__ __half g_yh[(size_t)ROWS*2*FF],g_yl[(size_t)ROWS*2*FF];
__device__ __half g_ch[(size_t)ROWS*DM],  g_cl[(size_t)ROWS*DM];
__device__ __half g_hh[(size_t)ROWS*DM],  g_hl[(size_t)ROWS*DM];
__device__ __half g_wsh[2*FF*DM], g_wsl[2*FF*DM];
__device__ __half g_wfh[DM*2*FF], g_wfl[DM*2*FF];
__device__ __half g_w1h[DM*DM],   g_w1l[DM*DM];
__device__ __half g_w2h[DM*DM],   g_w2l[DM*DM];
__device__ float g_w[2*TAPS*FF];
__device__ float g_errpart[1024];

// ---------------- PTX helpers ----------------
__device__ __forceinline__ uint32_t smem_u32(const void* p){
    uint32_t a; asm("{ .reg .u64 t; cvta.to.shared.u64 t, %1; cvt.u32.u64 %0, t; }":"=r"(a):"l"(p)); return a;
}
#define CPA16(dst,src) asm volatile("cp.async.cg.shared.global [%0],[%1],16;"::"r"(dst),"l"(src))
#define CPA_COMMIT()   asm volatile("cp.async.commit_group;":::"memory")
#define CPA_WAIT1()    asm volatile("cp.async.wait_group 1;":::"memory")
#define CPA_WAIT0()    asm volatile("cp.async.wait_group 0;":::"memory")

#define LDSM_X4(r0,r1,r2,r3,addr) \
    asm volatile("ldmatrix.sync.aligned.m8n8.x4.shared.b16 {%0,%1,%2,%3},[%4];" \
        : "=r"(r0),"=r"(r1),"=r"(r2),"=r"(r3) : "r"(addr))

#define MMA_F32(d,a,b) \
    asm volatile("mma.sync.aligned.m16n8k16.row.col.f32.f16.f16.f32 " \
        "{%0,%1,%2,%3},{%4,%5,%6,%7},{%8,%9},{%0,%1,%2,%3};" \
        : "+f"((d)[0]),"+f"((d)[1]),"+f"((d)[2]),"+f"((d)[3]) \
        : "r"((a)[0]),"r"((a)[1]),"r"((a)[2]),"r"((a)[3]),"r"((b)[0]),"r"((b)[1]))

#define MMA_F16(d,a,b) \
    asm volatile("mma.sync.aligned.m16n8k16.row.col.f16.f16.f16.f16 " \
        "{%0,%1},{%2,%3,%4,%5},{%6,%7},{%0,%1};" \
        : "+r"((d)[0]),"+r"((d)[1]) \
        : "r"((a)[0]),"r"((a)[1]),"r"((a)[2]),"r"((a)[3]),"r"((b)[0]),"r"((b)[1]))

__device__ __forceinline__ void split2h(float v, __half& h, __half& l){
    h = __float2half(v);
    l = __float2half((v - __half2float(h)) * LO_S);
}

// ---------------- block reduce (N threads, N/32 warps <= 16) ----------------
template<int WARPS>
__device__ __forceinline__ float block_sum(float v, float* red) {
    #pragma unroll
    for (int o = 16; o > 0; o >>= 1) v += __shfl_xor_sync(0xffffffffu, v, o);
    int lane = threadIdx.x & 31, w = threadIdx.x >> 5;
    if (lane == 0) red[w] = v;
    __syncthreads();
    if (w == 0) {
        float r = (lane < WARPS) ? red[lane] : 0.f;
        #pragma unroll
        for (int o = 16; o > 0; o >>= 1) r += __shfl_xor_sync(0xffffffffu, r, o);
        if (lane == 0) red[0] = r;
    }
    __syncthreads();
    float out = red[0];
    __syncthreads();
    return out;
}

// ---------------- FIR tap precompute ----------------
__global__ void prep_kernel(const float* __restrict__ log_decay,
                            const float* __restrict__ freq) {
    int f = threadIdx.x;
    float decay = 1.f / (1.f + expf(-log_decay[f]));
    float omega = tanhf(freq[f]) * 0.1f;
    float cr = cosf(omega), ci = sinf(omega);
    float Ar = decay * cr, Ai = decay * ci;
    float pr = 1.f, pi = 0.f;
    #pragma unroll 1
    for (int t = 0; t < TAPS; t++) {
        g_w[t*FF + f]           = pr*cr - pi*ci;
        g_w[TAPS*FF + t*FF + f] = pr*ci + pi*cr;
        float nr = pr*Ar - pi*Ai, ni = pr*Ai + pi*Ar;
        pr = nr; pi = ni;
    }
}

// ---------------- weight split ----------------
__global__ void wsplit_kernel(const float* __restrict__ w,
                              __half* __restrict__ h, __half* __restrict__ l, int n){
    int i = blockIdx.x*256 + threadIdx.x;
    if (i < n) { __half hi, lo; split2h(w[i], hi, lo); h[i] = hi; l[i] = lo; }
}

// ---------------- LayerNorm over D=1024 ----------------
template<bool SPLIT>
__global__ void ln_kernel(const float* __restrict__ x, const float* __restrict__ g,
                          const float* __restrict__ b, float* __restrict__ outf,
                          __half* __restrict__ oh, __half* __restrict__ ol) {
    __shared__ float red[8];
    int row = blockIdx.x, tid = threadIdx.x;
    float4 v = ((const float4*)(x + (size_t)row*DM))[tid];
    float mu = block_sum<8>(v.x + v.y + v.z + v.w, red) * (1.f/DM);
    float dx = v.x - mu, dy = v.y - mu, dz = v.z - mu, dw = v.w - mu;
    float var = block_sum<8>(dx*dx + dy*dy + dz*dz + dw*dw, red) * (1.f/DM);
    float rs = rsqrtf(var + LN_EPS);
    float4 gv = ((const float4*)g)[tid];
    float4 bv = ((const float4*)b)[tid];
    float o0 = dx*rs*gv.x + bv.x, o1 = dy*rs*gv.y + bv.y;
    float o2 = dz*rs*gv.z + bv.z, o3 = dw*rs*gv.w + bv.w;
    if (SPLIT) {
        __half h0,l0,h1,l1,h2,l2,h3,l3;
        split2h(o0,h0,l0); split2h(o1,h1,l1); split2h(o2,h2,l2); split2h(o3,h3,l3);
        size_t base = (size_t)row*DM + tid*4;
        ((__half2*)(oh+base))[0] = __halves2half2(h0,h1);
        ((__half2*)(oh+base))[1] = __halves2half2(h2,h3);
        ((__half2*)(ol+base))[0] = __halves2half2(l0,l1);
        ((__half2*)(ol+base))[1] = __halves2half2(l2,l3);
    } else {
        ((float4*)(outf + (size_t)row*DM))[tid] = make_float4(o0,o1,o2,o3);
    }
}

// ---------------- HMMA fp16 split GEMM: C[M,N] = A[M,K] * B[N,K]^T ---------
// hi pass f32-accum; two lo passes share one f16 accumulator (operands x2048).
// tile 128x128x32, 512 threads, 16 warps, warp tile 64x16, 2-stage cp.async.
#define ROWB 80u
#define TILEB (128u*ROWB)      /* 10240 */
#define STAGE (4u*TILEB)       /* 40960 */

template<bool BIAS, bool GELU, bool SPLIT, bool ERR>
__global__ void __launch_bounds__(512, 1) gemm_mma(
    const __half* __restrict__ Ah, const __half* __restrict__ Al,
    const __half* __restrict__ Bh, const __half* __restrict__ Bl,
    const float* __restrict__ bias,
    float* __restrict__ Cf, __half* __restrict__ Ch, __half* __restrict__ Cl,
    const float* __restrict__ td, const float* __restrict__ ew,
    int M, int N, int K)
{
    extern __shared__ char dsm[];
    __shared__ float red[16];
    const uint32_t sb = smem_u32(dsm);
    const uint32_t OAH = 0, OAL = TILEB, OBH = 2*TILEB, OBL = 3*TILEB;

    const int m0 = blockIdx.y * 128, n0 = blockIdx.x * 128;
    const int tid = threadIdx.x, lane = tid & 31, wid = tid >> 5;
    const int wm0 = (wid & 1) * 64, wn0 = (wid >> 1) * 16;
    const int NC = K >> 5;

    float    acc[4][2][4];
    uint32_t a16[4][2][2];
    #pragma unroll
    for (int i = 0; i < 4; i++)
        #pragma unroll
        for (int j = 0; j < 2; j++) {
            #pragma unroll
            for (int r = 0; r < 4; r++) acc[i][j][r] = 0.f;
            a16[i][j][0] = 0u; a16[i][j][1] = 0u;
        }

    // cp.async: one 16B granule per thread per tile
    const int lr = tid >> 2, lg = tid & 3;
    const char* pA  = (const char*)(Ah + (size_t)(m0 + lr)*K + lg*8);
    const char* pAl = (const char*)(Al + (size_t)(m0 + lr)*K + lg*8);
    const char* pB  = (const char*)(Bh + (size_t)(n0 + lr)*K + lg*8);
    const char* pBl = (const char*)(Bl + (size_t)(n0 + lr)*K + lg*8);
    const uint32_t dloc = (uint32_t)lr*ROWB + (uint32_t)lg*16u;

    auto load_stage = [&](int c){
        uint32_t s0 = sb + (uint32_t)(c & 1)*STAGE;
        size_t gb = (size_t)c * 64;           // 32 halfs = 64 bytes
        CPA16(s0 + OAH + dloc, pA  + gb);
        CPA16(s0 + OAL + dloc, pAl + gb);
        CPA16(s0 + OBH + dloc, pB  + gb);
        CPA16(s0 + OBL + dloc, pBl + gb);
        CPA_COMMIT();
    };

    const uint32_t a_row = (uint32_t)(wm0 + (lane & 15));
    const uint32_t a_kg  = (uint32_t)(lane >> 4);
    const uint32_t b_sel = (uint32_t)(lane >> 3);
    const uint32_t b_row = (uint32_t)(wn0 + ((b_sel >> 1) << 3) + (lane & 7));
    const uint32_t b_kg  = b_sel & 1u;

    load_stage(0);
    for (int c = 0; c < NC; c++) {
        if (c + 1 < NC) { load_stage(c + 1); CPA_WAIT1(); }
        else           { CPA_WAIT0(); }
        __syncthreads();
        uint32_t s0 = sb + (uint32_t)(c & 1)*STAGE;

        #pragma unroll
        for (int s = 0; s < 2; s++) {       // two k16 steps per chunk
            uint32_t ah[4][4], al[4][4], bh[2][2], bl[2][2];
            #pragma unroll
            for (int mi = 0; mi < 4; mi++) {
                uint32_t ad = s0 + (a_row + mi*16u)*ROWB + ((uint32_t)s*2u + a_kg)*16u;
                LDSM_X4(ah[mi][0], ah[mi][1], ah[mi][2], ah[mi][3], ad + OAH);
                LDSM_X4(al[mi][0], al[mi][1], al[mi][2], al[mi][3], ad + OAL);
            }
            {
                uint32_t bd = s0 + b_row*ROWB + ((uint32_t)s*2u + b_kg)*16u;
                LDSM_X4(bh[0][0], bh[0][1], bh[1][0], bh[1][1], bd + OBH);
                LDSM_X4(bl[0][0], bl[0][1], bl[1][0], bl[1][1], bd + OBL);
            }
            #pragma unroll
            for (int mi = 0; mi < 4; mi++)
                #pragma unroll
                for (int ni = 0; ni < 2; ni++) {
                    MMA_F32(acc[mi][ni], ah[mi], bh[ni]);
                    MMA_F16(a16[mi][ni], al[mi], bh[ni]);
                    MMA_F16(a16[mi][ni], ah[mi], bl[ni]);
                }
        }
        __syncthreads();
    }

    float sw = 0.f;
    if (ERR) sw = 1.f / (1.f + expf(-ew[0]));
    float esum = 0.f;

    const int er = lane >> 2, ec = (lane & 3) * 2;
    #pragma unroll
    for (int mi = 0; mi < 4; mi++) {
        #pragma unroll
        for (int half = 0; half < 2; half++) {
            int m = m0 + wm0 + mi*16 + er + half*8;
            #pragma unroll
            for (int ni = 0; ni < 2; ni++) {
                int n = n0 + wn0 + ni*8 + ec;
                float2 lo = __half22float2(*(__half2*)&a16[mi][ni][half]);
                float v0 = acc[mi][ni][half*2 + 0] + lo.x * LO_INV;
                float v1 = acc[mi][ni][half*2 + 1] + lo.y * LO_INV;
                if (BIAS) { v0 += __ldg(&bias[n]); v1 += __ldg(&bias[n+1]); }
                if (GELU) {
                    v0 = 0.5f * v0 * (1.f + erff(v0 * 0.70710678118654752f));
                    v1 = 0.5f * v1 * (1.f + erff(v1 * 0.70710678118654752f));
                }
                if (ERR) {
                    float2 t = *(const float2*)(td + (size_t)m*N + n);
                    float e0 = fminf(fmaxf(v0 - t.x, -1.f), 1.f);
                    float e1 = fminf(fmaxf(v1 - t.y, -1.f), 1.f);
                    esum += e0*e0 + e1*e1;
                    v0 -= sw*e0; v1 -= sw*e1;
                }
                if (ERR || !SPLIT)
                    *(float2*)(Cf + (size_t)m*N + n) = make_float2(v0, v1);
                if (SPLIT) {
                    __half h0,l0,h1,l1;
                    split2h(v0,h0,l0); split2h(v1,h1,l1);
                    *(__half2*)(Ch + (size_t)m*N + n) = __halves2half2(h0,h1);
                    *(__half2*)(Cl + (size_t)m*N + n) = __halves2half2(l0,l1);
                }
            }
        }
    }
    if (ERR) {
        float s = block_sum<16>(esum, red);
        if (tid == 0) g_errpart[blockIdx.y * gridDim.x + blockIdx.x] = s;
    }
}

// ---------------- 32-tap complex causal FIR along S (fp16-split output) ----
__global__ void conv_kernel(const float* __restrict__ u,
                            __half* __restrict__ yh, __half* __restrict__ yl) {
    __shared__ float sur[95*32], sui[95*32];
    __shared__ float swr[TAPS*32], swi[TAPS*32];
    const int f0 = blockIdx.x * 32;
    const int t0 = blockIdx.y * 64;
    const int b  = blockIdx.z;
    const int tid = threadIdx.x;

    for (int i = tid; i < 95*32; i += 256) {
        int tt = i >> 5, fl = i & 31;
        int tg = t0 - 31 + tt;
        float vr = 0.f, vi = 0.f;
        if (tg >= 0) {
            size_t base = ((size_t)(b*SEQ + tg))*(2*FF) + f0 + fl;
            vr = u[base]; vi = u[base + FF];
        }
        sur[i] = vr; sui[i] = vi;
    }
    for (int i = tid; i < TAPS*32; i += 256) {
        int tt = i >> 5, fl = i & 31;
        swr[i] = g_w[tt*FF + f0 + fl];
        swi[i] = g_w[TAPS*FF + tt*FF + f0 + fl];
    }
    __syncthreads();

    const int fl = tid & 31, tr = tid >> 5;
    #pragma unroll
    for (int j = 0; j < 8; j++) {
        int tl = tr*8 + j;
        float ar = 0.f, ai = 0.f;
        #pragma unroll
        for (int t = 0; t < TAPS; t++) {
            int idx = (31 + tl - t)*32 + fl;
            float ur = sur[idx], ui = sui[idx];
            float wr = swr[t*32 + fl], wi = swi[t*32 + fl];
            ar += ur*wr - ui*wi;
            ai += ur*wi + ui*wr;
        }
        size_t ob = ((size_t)(b*SEQ + t0 + tl))*(2*FF) + f0 + fl;
        __half h, l;
        split2h(ar, h, l); yh[ob] = h;      yl[ob] = l;
        split2h(ai, h, l); yh[ob + FF] = h; yl[ob + FF] = l;
    }
}

__global__ void fin_kernel(float* __restrict__ out_scalar) {
    __shared__ float red[8];
    float s = 0.f;
    for (int i = threadIdx.x; i < 1024; i += 256) s += g_errpart[i];
    s = block_sum<8>(s, red);
    if (threadIdx.x == 0) {
        float pe = s / (float)((size_t)ROWS * DM);
        out_scalar[0] = fminf(fmaxf(pe, 0.f), 1.f);
    }
}

// ---------------- launch ----------------
extern "C" void kernel_launch(void* const* d_in, const int* in_sizes, int n_in,
                              void* d_out, int out_size) {
    const float* bu    = (const float*)d_in[0];
    const float* td    = (const float*)d_in[1];
    const float* Wspec = (const float*)d_in[2];
    const float* ldec  = (const float*)d_in[3];
    const float* freq  = (const float*)d_in[4];
    const float* Wfrom = (const float*)d_in[5];
    const float* l1g   = (const float*)d_in[6];
    const float* l1b   = (const float*)d_in[7];
    const float* W1    = (const float*)d_in[8];
    const float* b1    = (const float*)d_in[9];
    const float* W2    = (const float*)d_in[10];
    const float* b2    = (const float*)d_in[11];
    const float* l2g   = (const float*)d_in[12];
    const float* l2b   = (const float*)d_in[13];
    const float* ew    = (const float*)d_in[14];

    float* out       = (float*)d_out;
    float* corrected = out;
    float* nextpred  = out + (size_t)ROWS*DM;
    float* pe        = out + 2*(size_t)ROWS*DM;

    float *spec, *h2;
    __half *xh,*xl,*yh,*yl,*ch,*cl,*hh,*hl;
    __half *wsh,*wsl,*wfh,*wfl,*w1h,*w1l,*w2h,*w2l;
    cudaGetSymbolAddress((void**)&spec,   g_spec);
    cudaGetSymbolAddress((void**)&h2,     g_h2);
    cudaGetSymbolAddress((void**)&xh, g_xh); cudaGetSymbolAddress((void**)&xl, g_xl);
    cudaGetSymbolAddress((void**)&yh, g_yh); cudaGetSymbolAddress((void**)&yl, g_yl);
    cudaGetSymbolAddress((void**)&ch, g_ch); cudaGetSymbolAddress((void**)&cl, g_cl);
    cudaGetSymbolAddress((void**)&hh, g_hh); cudaGetSymbolAddress((void**)&hl, g_hl);
    cudaGetSymbolAddress((void**)&wsh, g_wsh); cudaGetSymbolAddress((void**)&wsl, g_wsl);
    cudaGetSymbolAddress((void**)&wfh, g_wfh); cudaGetSymbolAddress((void**)&wfl, g_wfl);
    cudaGetSymbolAddress((void**)&w1h, g_w1h); cudaGetSymbolAddress((void**)&w1l, g_w1l);
    cudaGetSymbolAddress((void**)&w2h, g_w2h); cudaGetSymbolAddress((void**)&w2l, g_w2l);

    const int SMEM_BYTES = 2 * (int)STAGE;   // 81920
    cudaFuncSetAttribute(gemm_mma<false,false,false,false>, cudaFuncAttributeMaxDynamicSharedMemorySize, SMEM_BYTES);
    cudaFuncSetAttribute(gemm_mma<false,false,true ,true >, cudaFuncAttributeMaxDynamicSharedMemorySize, SMEM_BYTES);
    cudaFuncSetAttribute(gemm_mma<true ,true ,true ,false>, cudaFuncAttributeMaxDynamicSharedMemorySize, SMEM_BYTES);
    cudaFuncSetAttribute(gemm_mma<true ,false,false,false>, cudaFuncAttributeMaxDynamicSharedMemorySize, SMEM_BYTES);

    prep_kernel<<<1, 256>>>(ldec, freq);
    wsplit_kernel<<<(2*FF*DM+255)/256, 256>>>(Wspec, wsh, wsl, 2*FF*DM);
    wsplit_kernel<<<(DM*2*FF+255)/256, 256>>>(Wfrom, wfh, wfl, DM*2*FF);
    wsplit_kernel<<<(DM*DM+255)/256, 256>>>(W1, w1h, w1l, DM*DM);
    wsplit_kernel<<<(DM*DM+255)/256, 256>>>(W2, w2h, w2l, DM*DM);

    ln_kernel<true><<<ROWS, 256>>>(bu, l1g, l1b, nullptr, xh, xl);

    gemm_mma<false,false,false,false><<<dim3((2*FF)/128, ROWS/128), 512, SMEM_BYTES>>>(
        xh, xl, wsh, wsl, nullptr, spec, nullptr, nullptr, nullptr, nullptr, ROWS, 2*FF, DM);

    conv_kernel<<<dim3(FF/32, SEQ/64, BSZ), 256>>>(spec, yh, yl);

    // GEMM2 fused with error/corrected/split + per-block error sums
    gemm_mma<false,false,true,true><<<dim3(DM/128, ROWS/128), 512, SMEM_BYTES>>>(
        yh, yl, wfh, wfl, nullptr, corrected, ch, cl, td, ew, ROWS, DM, 2*FF);

    fin_kernel<<<1, 256>>>(pe);

    gemm_mma<true,true,true,false><<<dim3(DM/128, ROWS/128), 512, SMEM_BYTES>>>(
        ch, cl, w1h, w1l, b1, nullptr, hh, hl, nullptr, nullptr, ROWS, DM, DM);

    gemm_mma<true,false,false,false><<<dim3(DM/128, ROWS/128), 512, SMEM_BYTES>>>(
        hh, hl, w2h, w2l, b2, h2, nullptr, nullptr, nullptr, nullptr, ROWS, DM, DM);

    ln_kernel<false><<<ROWS, 256>>>(h2, l2g, l2b, nextpred, nullptr, nullptr);
}

// round 5
// speedup vs baseline: 2.0804x; 1.1263x over previous
#include <cuda_runtime.h>
#include <cuda_fp16.h>
#include <math.h>
#include <stdint.h>

#define BSZ  4
#define SEQ  4096
#define DM   1024
#define FF   256
#define ROWS (BSZ*SEQ)            /* 16384 */
#define TAPS 32
#define LN_EPS 1e-5f
#define LO_S   2048.0f
#define LO_INV 4.8828125e-4f

// ---------------- scratch (device globals: no alloc allowed) ----------------
__device__ float g_spec  [(size_t)ROWS*2*FF];   // fp32 GEMM1 out (conv input)
__device__ float g_h2    [(size_t)ROWS*DM];     // fp32 GEMM4 out
__device__ __half g_xh[(size_t)ROWS*DM],  g_xl[(size_t)ROWS*DM];
__device__ __half g_yh[(size_t)ROWS*2*FF],g_yl[(size_t)ROWS*2*FF];
__device__ __half g_ch[(size_t)ROWS*DM],  g_cl[(size_t)ROWS*DM];
__device__ __half g_hh[(size_t)ROWS*DM],  g_hl[(size_t)ROWS*DM];
__device__ __half g_wsh[2*FF*DM], g_wsl[2*FF*DM];
__device__ __half g_wfh[DM*2*FF], g_wfl[DM*2*FF];
__device__ __half g_w1h[DM*DM],   g_w1l[DM*DM];
__device__ __half g_w2h[DM*DM],   g_w2l[DM*DM];
__device__ float g_w[2*TAPS*FF];
__device__ float g_errpart[1024];

// ---------------- PTX helpers ----------------
__device__ __forceinline__ uint32_t smem_u32(const void* p){
    uint32_t a; asm("{ .reg .u64 t; cvta.to.shared.u64 t, %1; cvt.u32.u64 %0, t; }":"=r"(a):"l"(p)); return a;
}
#define CPA16(dst,src) asm volatile("cp.async.cg.shared.global [%0],[%1],16;"::"r"(dst),"l"(src))
#define CPA_COMMIT()   asm volatile("cp.async.commit_group;":::"memory")
#define CPA_WAIT1()    asm volatile("cp.async.wait_group 1;":::"memory")
#define CPA_WAIT0()    asm volatile("cp.async.wait_group 0;":::"memory")

#define LDSM_X4(r0,r1,r2,r3,addr) \
    asm volatile("ldmatrix.sync.aligned.m8n8.x4.shared.b16 {%0,%1,%2,%3},[%4];" \
        : "=r"(r0),"=r"(r1),"=r"(r2),"=r"(r3) : "r"(addr))

#define MMA_F32(d,a,b) \
    asm volatile("mma.sync.aligned.m16n8k16.row.col.f32.f16.f16.f32 " \
        "{%0,%1,%2,%3},{%4,%5,%6,%7},{%8,%9},{%0,%1,%2,%3};" \
        : "+f"((d)[0]),"+f"((d)[1]),"+f"((d)[2]),"+f"((d)[3]) \
        : "r"((a)[0]),"r"((a)[1]),"r"((a)[2]),"r"((a)[3]),"r"((b)[0]),"r"((b)[1]))

#define MMA_F16(d,a,b) \
    asm volatile("mma.sync.aligned.m16n8k16.row.col.f16.f16.f16.f16 " \
        "{%0,%1},{%2,%3,%4,%5},{%6,%7},{%0,%1};" \
        : "+r"((d)[0]),"+r"((d)[1]) \
        : "r"((a)[0]),"r"((a)[1]),"r"((a)[2]),"r"((a)[3]),"r"((b)[0]),"r"((b)[1]))

__device__ __forceinline__ void split2h(float v, __half& h, __half& l){
    h = __float2half(v);
    l = __float2half((v - __half2float(h)) * LO_S);
}

// ---------------- block reduce ----------------
template<int WARPS>
__device__ __forceinline__ float block_sum(float v, float* red) {
    #pragma unroll
    for (int o = 16; o > 0; o >>= 1) v += __shfl_xor_sync(0xffffffffu, v, o);
    int lane = threadIdx.x & 31, w = threadIdx.x >> 5;
    if (lane == 0) red[w] = v;
    __syncthreads();
    if (w == 0) {
        float r = (lane < WARPS) ? red[lane] : 0.f;
        #pragma unroll
        for (int o = 16; o > 0; o >>= 1) r += __shfl_xor_sync(0xffffffffu, r, o);
        if (lane == 0) red[0] = r;
    }
    __syncthreads();
    float out = red[0];
    __syncthreads();
    return out;
}

// ---------------- FIR tap precompute ----------------
__global__ void prep_kernel(const float* __restrict__ log_decay,
                            const float* __restrict__ freq) {
    int f = threadIdx.x;
    float decay = 1.f / (1.f + expf(-log_decay[f]));
    float omega = tanhf(freq[f]) * 0.1f;
    float cr = cosf(omega), ci = sinf(omega);
    float Ar = decay * cr, Ai = decay * ci;
    float pr = 1.f, pi = 0.f;
    #pragma unroll 1
    for (int t = 0; t < TAPS; t++) {
        g_w[t*FF + f]           = pr*cr - pi*ci;
        g_w[TAPS*FF + t*FF + f] = pr*ci + pi*cr;
        float nr = pr*Ar - pi*Ai, ni = pr*Ai + pi*Ar;
        pr = nr; pi = ni;
    }
}

// ---------------- weight split ----------------
__global__ void wsplit_kernel(const float* __restrict__ w,
                              __half* __restrict__ h, __half* __restrict__ l, int n){
    int i = blockIdx.x*256 + threadIdx.x;
    if (i < n) { __half hi, lo; split2h(w[i], hi, lo); h[i] = hi; l[i] = lo; }
}

// ---------------- LayerNorm over D=1024 ----------------
template<bool SPLIT>
__global__ void ln_kernel(const float* __restrict__ x, const float* __restrict__ g,
                          const float* __restrict__ b, float* __restrict__ outf,
                          __half* __restrict__ oh, __half* __restrict__ ol) {
    __shared__ float red[8];
    int row = blockIdx.x, tid = threadIdx.x;
    float4 v = ((const float4*)(x + (size_t)row*DM))[tid];
    float mu = block_sum<8>(v.x + v.y + v.z + v.w, red) * (1.f/DM);
    float dx = v.x - mu, dy = v.y - mu, dz = v.z - mu, dw = v.w - mu;
    float var = block_sum<8>(dx*dx + dy*dy + dz*dz + dw*dw, red) * (1.f/DM);
    float rs = rsqrtf(var + LN_EPS);
    float4 gv = ((const float4*)g)[tid];
    float4 bv = ((const float4*)b)[tid];
    float o0 = dx*rs*gv.x + bv.x, o1 = dy*rs*gv.y + bv.y;
    float o2 = dz*rs*gv.z + bv.z, o3 = dw*rs*gv.w + bv.w;
    if (SPLIT) {
        __half h0,l0,h1,l1,h2,l2,h3,l3;
        split2h(o0,h0,l0); split2h(o1,h1,l1); split2h(o2,h2,l2); split2h(o3,h3,l3);
        size_t base = (size_t)row*DM + tid*4;
        ((__half2*)(oh+base))[0] = __halves2half2(h0,h1);
        ((__half2*)(oh+base))[1] = __halves2half2(h2,h3);
        ((__half2*)(ol+base))[0] = __halves2half2(l0,l1);
        ((__half2*)(ol+base))[1] = __halves2half2(l2,l3);
    } else {
        ((float4*)(outf + (size_t)row*DM))[tid] = make_float4(o0,o1,o2,o3);
    }
}

// ---------------- HMMA fp16 split GEMM: C[M,N] = A[M,K] * B[N,K]^T ---------
// hi pass f32-accum; two lo passes share one f16 accumulator (operands x2048).
// tile 128x128x32, 512 threads, 16 warps, warp tile 64x16.
// 3-stage cp.async pipeline, ONE __syncthreads per chunk.
#define ROWB 80u
#define TILEB (128u*ROWB)      /* 10240 */
#define STAGE (4u*TILEB)       /* 40960 */
#define NSTG  3

template<bool BIAS, bool GELU, bool SPLIT, bool ERR>
__global__ void __launch_bounds__(512, 1) gemm_mma(
    const __half* __restrict__ Ah, const __half* __restrict__ Al,
    const __half* __restrict__ Bh, const __half* __restrict__ Bl,
    const float* __restrict__ bias,
    float* __restrict__ Cf, __half* __restrict__ Ch, __half* __restrict__ Cl,
    const float* __restrict__ td, const float* __restrict__ ew,
    int M, int N, int K)
{
    extern __shared__ char dsm[];
    __shared__ float red[16];
    const uint32_t sb = smem_u32(dsm);
    const uint32_t OAH = 0, OAL = TILEB, OBH = 2*TILEB, OBL = 3*TILEB;

    const int m0 = blockIdx.y * 128, n0 = blockIdx.x * 128;
    const int tid = threadIdx.x, lane = tid & 31, wid = tid >> 5;
    const int wm0 = (wid & 1) * 64, wn0 = (wid >> 1) * 16;
    const int NC = K >> 5;

    float    acc[4][2][4];
    uint32_t a16[4][2][2];
    #pragma unroll
    for (int i = 0; i < 4; i++)
        #pragma unroll
        for (int j = 0; j < 2; j++) {
            #pragma unroll
            for (int r = 0; r < 4; r++) acc[i][j][r] = 0.f;
            a16[i][j][0] = 0u; a16[i][j][1] = 0u;
        }

    // cp.async: one 16B granule per thread per tile
    const int lr = tid >> 2, lg = tid & 3;
    const char* pA  = (const char*)(Ah + (size_t)(m0 + lr)*K + lg*8);
    const char* pAl = (const char*)(Al + (size_t)(m0 + lr)*K + lg*8);
    const char* pB  = (const char*)(Bh + (size_t)(n0 + lr)*K + lg*8);
    const char* pBl = (const char*)(Bl + (size_t)(n0 + lr)*K + lg*8);
    const uint32_t dloc = (uint32_t)lr*ROWB + (uint32_t)lg*16u;

    auto load_stage = [&](int slot, int c){
        uint32_t s0 = sb + (uint32_t)slot*STAGE;
        size_t gb = (size_t)c * 64;           // 32 halfs = 64 bytes
        CPA16(s0 + OAH + dloc, pA  + gb);
        CPA16(s0 + OAL + dloc, pAl + gb);
        CPA16(s0 + OBH + dloc, pB  + gb);
        CPA16(s0 + OBL + dloc, pBl + gb);
        CPA_COMMIT();
    };

    const uint32_t a_row = (uint32_t)(wm0 + (lane & 15));
    const uint32_t a_kg  = (uint32_t)(lane >> 4);
    const uint32_t b_sel = (uint32_t)(lane >> 3);
    const uint32_t b_row = (uint32_t)(wn0 + ((b_sel >> 1) << 3) + (lane & 7));
    const uint32_t b_kg  = b_sel & 1u;

    load_stage(0, 0);
    load_stage(1, 1);
    int cs = 0, ls = 2;
    for (int c = 0; c < NC; c++) {
        if (c < NC - 1) CPA_WAIT1(); else CPA_WAIT0();
        __syncthreads();                       // all warps done with chunk c-1
        if (c + 2 < NC) {                      // slot ls == (c-1)%3, now free
            load_stage(ls, c + 2);
            ls = (ls == 2) ? 0 : ls + 1;
        }
        uint32_t s0 = sb + (uint32_t)cs*STAGE;
        cs = (cs == 2) ? 0 : cs + 1;

        #pragma unroll
        for (int s = 0; s < 2; s++) {          // two k16 steps per chunk
            uint32_t ah[4][4], al[4][4], bh[2][2], bl[2][2];
            #pragma unroll
            for (int mi = 0; mi < 4; mi++) {
                uint32_t ad = s0 + (a_row + mi*16u)*ROWB + ((uint32_t)s*2u + a_kg)*16u;
                LDSM_X4(ah[mi][0], ah[mi][1], ah[mi][2], ah[mi][3], ad + OAH);
                LDSM_X4(al[mi][0], al[mi][1], al[mi][2], al[mi][3], ad + OAL);
            }
            {
                uint32_t bd = s0 + b_row*ROWB + ((uint32_t)s*2u + b_kg)*16u;
                LDSM_X4(bh[0][0], bh[0][1], bh[1][0], bh[1][1], bd + OBH);
                LDSM_X4(bl[0][0], bl[0][1], bl[1][0], bl[1][1], bd + OBL);
            }
            #pragma unroll
            for (int mi = 0; mi < 4; mi++)
                #pragma unroll
                for (int ni = 0; ni < 2; ni++) {
                    MMA_F32(acc[mi][ni], ah[mi], bh[ni]);
                    MMA_F16(a16[mi][ni], al[mi], bh[ni]);
                    MMA_F16(a16[mi][ni], ah[mi], bl[ni]);
                }
        }
    }

    float sw = 0.f;
    if (ERR) sw = 1.f / (1.f + expf(-ew[0]));
    float esum = 0.f;

    const int er = lane >> 2, ec = (lane & 3) * 2;
    #pragma unroll
    for (int mi = 0; mi < 4; mi++) {
        #pragma unroll
        for (int half = 0; half < 2; half++) {
            int m = m0 + wm0 + mi*16 + er + half*8;
            #pragma unroll
            for (int ni = 0; ni < 2; ni++) {
                int n = n0 + wn0 + ni*8 + ec;
                float2 lo = __half22float2(*(__half2*)&a16[mi][ni][half]);
                float v0 = acc[mi][ni][half*2 + 0] + lo.x * LO_INV;
                float v1 = acc[mi][ni][half*2 + 1] + lo.y * LO_INV;
                if (BIAS) { v0 += __ldg(&bias[n]); v1 += __ldg(&bias[n+1]); }
                if (GELU) {
                    v0 = 0.5f * v0 * (1.f + erff(v0 * 0.70710678118654752f));
                    v1 = 0.5f * v1 * (1.f + erff(v1 * 0.70710678118654752f));
                }
                if (ERR) {
                    float2 t = *(const float2*)(td + (size_t)m*N + n);
                    float e0 = fminf(fmaxf(v0 - t.x, -1.f), 1.f);
                    float e1 = fminf(fmaxf(v1 - t.y, -1.f), 1.f);
                    esum += e0*e0 + e1*e1;
                    v0 -= sw*e0; v1 -= sw*e1;
                }
                if (ERR || !SPLIT)
                    *(float2*)(Cf + (size_t)m*N + n) = make_float2(v0, v1);
                if (SPLIT) {
                    __half h0,l0,h1,l1;
                    split2h(v0,h0,l0); split2h(v1,h1,l1);
                    *(__half2*)(Ch + (size_t)m*N + n) = __halves2half2(h0,h1);
                    *(__half2*)(Cl + (size_t)m*N + n) = __halves2half2(l0,l1);
                }
            }
        }
    }
    if (ERR) {
        float s = block_sum<16>(esum, red);
        if (tid == 0) g_errpart[blockIdx.y * gridDim.x + blockIdx.x] = s;
    }
}

// ---------------- 32-tap complex causal FIR along S (fp16-split output) ----
// tile 32 t x 32 f, 256 threads, 4 outputs/thread.
__global__ void __launch_bounds__(256) conv_kernel(
    const float* __restrict__ u, __half* __restrict__ yh, __half* __restrict__ yl) {
    __shared__ float sur[63*32], sui[63*32];
    __shared__ float swr[TAPS*32], swi[TAPS*32];
    const int f0 = blockIdx.x * 32;
    const int t0 = blockIdx.y * 32;
    const int b  = blockIdx.z;
    const int tid = threadIdx.x;

    for (int i = tid; i < 63*32; i += 256) {
        int tt = i >> 5, fl = i & 31;
        int tg = t0 - 31 + tt;
        float vr = 0.f, vi = 0.f;
        if (tg >= 0) {
            size_t base = ((size_t)(b*SEQ + tg))*(2*FF) + f0 + fl;
            vr = u[base]; vi = u[base + FF];
        }
        sur[i] = vr; sui[i] = vi;
    }
    for (int i = tid; i < TAPS*32; i += 256) {
        int tt = i >> 5, fl = i & 31;
        swr[i] = g_w[tt*FF + f0 + fl];
        swi[i] = g_w[TAPS*FF + tt*FF + f0 + fl];
    }
    __syncthreads();

    const int fl = tid & 31, tr = tid >> 5;
    #pragma unroll
    for (int j = 0; j < 4; j++) {
        int tl = tr*4 + j;
        float ar = 0.f, ai = 0.f;
        #pragma unroll
        for (int t = 0; t < TAPS; t++) {
            int idx = (31 + tl - t)*32 + fl;
            float ur = sur[idx], ui = sui[idx];
            float wr = swr[t*32 + fl], wi = swi[t*32 + fl];
            ar += ur*wr - ui*wi;
            ai += ur*wi + ui*wr;
        }
        size_t ob = ((size_t)(b*SEQ + t0 + tl))*(2*FF) + f0 + fl;
        __half h, l;
        split2h(ar, h, l); yh[ob] = h;      yl[ob] = l;
        split2h(ai, h, l); yh[ob + FF] = h; yl[ob + FF] = l;
    }
}

__global__ void fin_kernel(float* __restrict__ out_scalar) {
    __shared__ float red[8];
    float s = 0.f;
    for (int i = threadIdx.x; i < 1024; i += 256) s += g_errpart[i];
    s = block_sum<8>(s, red);
    if (threadIdx.x == 0) {
        float pe = s / (float)((size_t)ROWS * DM);
        out_scalar[0] = fminf(fmaxf(pe, 0.f), 1.f);
    }
}

// ---------------- launch ----------------
extern "C" void kernel_launch(void* const* d_in, const int* in_sizes, int n_in,
                              void* d_out, int out_size) {
    const float* bu    = (const float*)d_in[0];
    const float* td    = (const float*)d_in[1];
    const float* Wspec = (const float*)d_in[2];
    const float* ldec  = (const float*)d_in[3];
    const float* freq  = (const float*)d_in[4];
    const float* Wfrom = (const float*)d_in[5];
    const float* l1g   = (const float*)d_in[6];
    const float* l1b   = (const float*)d_in[7];
    const float* W1    = (const float*)d_in[8];
    const float* b1    = (const float*)d_in[9];
    const float* W2    = (const float*)d_in[10];
    const float* b2    = (const float*)d_in[11];
    const float* l2g   = (const float*)d_in[12];
    const float* l2b   = (const float*)d_in[13];
    const float* ew    = (const float*)d_in[14];

    float* out       = (float*)d_out;
    float* corrected = out;
    float* nextpred  = out + (size_t)ROWS*DM;
    float* pe        = out + 2*(size_t)ROWS*DM;

    float *spec, *h2;
    __half *xh,*xl,*yh,*yl,*ch,*cl,*hh,*hl;
    __half *wsh,*wsl,*wfh,*wfl,*w1h,*w1l,*w2h,*w2l;
    cudaGetSymbolAddress((void**)&spec,   g_spec);
    cudaGetSymbolAddress((void**)&h2,     g_h2);
    cudaGetSymbolAddress((void**)&xh, g_xh); cudaGetSymbolAddress((void**)&xl, g_xl);
    cudaGetSymbolAddress((void**)&yh, g_yh); cudaGetSymbolAddress((void**)&yl, g_yl);
    cudaGetSymbolAddress((void**)&ch, g_ch); cudaGetSymbolAddress((void**)&cl, g_cl);
    cudaGetSymbolAddress((void**)&hh, g_hh); cudaGetSymbolAddress((void**)&hl, g_hl);
    cudaGetSymbolAddress((void**)&wsh, g_wsh); cudaGetSymbolAddress((void**)&wsl, g_wsl);
    cudaGetSymbolAddress((void**)&wfh, g_wfh); cudaGetSymbolAddress((void**)&wfl, g_wfl);
    cudaGetSymbolAddress((void**)&w1h, g_w1h); cudaGetSymbolAddress((void**)&w1l, g_w1l);
    cudaGetSymbolAddress((void**)&w2h, g_w2h); cudaGetSymbolAddress((void**)&w2l, g_w2l);

    const int SMEM_BYTES = NSTG * (int)STAGE;   // 122880
    cudaFuncSetAttribute(gemm_mma<false,false,false,false>, cudaFuncAttributeMaxDynamicSharedMemorySize, SMEM_BYTES);
    cudaFuncSetAttribute(gemm_mma<false,false,true ,true >, cudaFuncAttributeMaxDynamicSharedMemorySize, SMEM_BYTES);
    cudaFuncSetAttribute(gemm_mma<true ,true ,true ,false>, cudaFuncAttributeMaxDynamicSharedMemorySize, SMEM_BYTES);
    cudaFuncSetAttribute(gemm_mma<true ,false,false,false>, cudaFuncAttributeMaxDynamicSharedMemorySize, SMEM_BYTES);

    prep_kernel<<<1, 256>>>(ldec, freq);
    wsplit_kernel<<<(2*FF*DM+255)/256, 256>>>(Wspec, wsh, wsl, 2*FF*DM);
    wsplit_kernel<<<(DM*2*FF+255)/256, 256>>>(Wfrom, wfh, wfl, DM*2*FF);
    wsplit_kernel<<<(DM*DM+255)/256, 256>>>(W1, w1h, w1l, DM*DM);
    wsplit_kernel<<<(DM*DM+255)/256, 256>>>(W2, w2h, w2l, DM*DM);

    ln_kernel<true><<<ROWS, 256>>>(bu, l1g, l1b, nullptr, xh, xl);

    gemm_mma<false,false,false,false><<<dim3((2*FF)/128, ROWS/128), 512, SMEM_BYTES>>>(
        xh, xl, wsh, wsl, nullptr, spec, nullptr, nullptr, nullptr, nullptr, ROWS, 2*FF, DM);

    conv_kernel<<<dim3(FF/32, SEQ/32, BSZ), 256>>>(spec, yh, yl);

    // GEMM2 fused with error/corrected/split + per-block error sums
    gemm_mma<false,false,true,true><<<dim3(DM/128, ROWS/128), 512, SMEM_BYTES>>>(
        yh, yl, wfh, wfl, nullptr, corrected, ch, cl, td, ew, ROWS, DM, 2*FF);

    fin_kernel<<<1, 256>>>(pe);

    gemm_mma<true,true,true,false><<<dim3(DM/128, ROWS/128), 512, SMEM_BYTES>>>(
        ch, cl, w1h, w1l, b1, nullptr, hh, hl, nullptr, nullptr, ROWS, DM, DM);

    gemm_mma<true,false,false,false><<<dim3(DM/128, ROWS/128), 512, SMEM_BYTES>>>(
        hh, hl, w2h, w2l, b2, h2, nullptr, nullptr, nullptr, nullptr, ROWS, DM, DM);

    ln_kernel<false><<<ROWS, 256>>>(h2, l2g, l2b, nextpred, nullptr, nullptr);
}

// round 6
// speedup vs baseline: 2.1440x; 1.0306x over previous
#include <cuda_runtime.h>
#include <cuda_fp16.h>
#include <math.h>
#include <stdint.h>

#define BSZ  4
#define SEQ  4096
#define DM   1024
#define FF   256
#define ROWS (BSZ*SEQ)            /* 16384 */
#define TAPS 32
#define LN_EPS 1e-5f
#define LO_S   2048.0f
#define LO_INV 4.8828125e-4f

// ---------------- scratch (device globals: no alloc allowed) ----------------
__device__ float g_spec  [(size_t)ROWS*2*FF];   // fp32 GEMM1 out (conv input)
__device__ float g_h2    [(size_t)ROWS*DM];     // fp32 GEMM4 out
__device__ __half g_xh[(size_t)ROWS*DM],  g_xl[(size_t)ROWS*DM];
__device__ __half g_yh[(size_t)ROWS*2*FF],g_yl[(size_t)ROWS*2*FF];
__device__ __half g_ch[(size_t)ROWS*DM],  g_cl[(size_t)ROWS*DM];
__device__ __half g_hh[(size_t)ROWS*DM],  g_hl[(size_t)ROWS*DM];
__device__ __half g_wsh[2*FF*DM], g_wsl[2*FF*DM];
__device__ __half g_wfh[DM*2*FF], g_wfl[DM*2*FF];
__device__ __half g_w1h[DM*DM],   g_w1l[DM*DM];
__device__ __half g_w2h[DM*DM],   g_w2l[DM*DM];
__device__ float g_w[2*TAPS*FF];
__device__ float g_errpart[1024];

// ---------------- PTX helpers ----------------
__device__ __forceinline__ uint32_t smem_u32(const void* p){
    uint32_t a; asm("{ .reg .u64 t; cvta.to.shared.u64 t, %1; cvt.u32.u64 %0, t; }":"=r"(a):"l"(p)); return a;
}
#define CPA16(dst,src) asm volatile("cp.async.cg.shared.global [%0],[%1],16;"::"r"(dst),"l"(src))
#define CPA_COMMIT()   asm volatile("cp.async.commit_group;":::"memory")
#define CPA_WAIT1()    asm volatile("cp.async.wait_group 1;":::"memory")
#define CPA_WAIT0()    asm volatile("cp.async.wait_group 0;":::"memory")

#define LDSM_X4(r0,r1,r2,r3,addr) \
    asm volatile("ldmatrix.sync.aligned.m8n8.x4.shared.b16 {%0,%1,%2,%3},[%4];" \
        : "=r"(r0),"=r"(r1),"=r"(r2),"=r"(r3) : "r"(addr))

#define MMA_F32(d,a,b) \
    asm volatile("mma.sync.aligned.m16n8k16.row.col.f32.f16.f16.f32 " \
        "{%0,%1,%2,%3},{%4,%5,%6,%7},{%8,%9},{%0,%1,%2,%3};" \
        : "+f"((d)[0]),"+f"((d)[1]),"+f"((d)[2]),"+f"((d)[3]) \
        : "r"((a)[0]),"r"((a)[1]),"r"((a)[2]),"r"((a)[3]),"r"((b)[0]),"r"((b)[1]))

#define MMA_F16(d,a,b) \
    asm volatile("mma.sync.aligned.m16n8k16.row.col.f16.f16.f16.f16 " \
        "{%0,%1},{%2,%3,%4,%5},{%6,%7},{%0,%1};" \
        : "+r"((d)[0]),"+r"((d)[1]) \
        : "r"((a)[0]),"r"((a)[1]),"r"((a)[2]),"r"((a)[3]),"r"((b)[0]),"r"((b)[1]))

__device__ __forceinline__ void split2h(float v, __half& h, __half& l){
    h = __float2half(v);
    l = __float2half((v - __half2float(h)) * LO_S);
}

// ---------------- block reduce ----------------
template<int WARPS>
__device__ __forceinline__ float block_sum(float v, float* red) {
    #pragma unroll
    for (int o = 16; o > 0; o >>= 1) v += __shfl_xor_sync(0xffffffffu, v, o);
    int lane = threadIdx.x & 31, w = threadIdx.x >> 5;
    if (lane == 0) red[w] = v;
    __syncthreads();
    if (w == 0) {
        float r = (lane < WARPS) ? red[lane] : 0.f;
        #pragma unroll
        for (int o = 16; o > 0; o >>= 1) r += __shfl_xor_sync(0xffffffffu, r, o);
        if (lane == 0) red[0] = r;
    }
    __syncthreads();
    float out = red[0];
    __syncthreads();
    return out;
}

// ---------------- FIR tap precompute ----------------
__global__ void prep_kernel(const float* __restrict__ log_decay,
                            const float* __restrict__ freq) {
    int f = threadIdx.x;
    float decay = 1.f / (1.f + expf(-log_decay[f]));
    float omega = tanhf(freq[f]) * 0.1f;
    float cr = cosf(omega), ci = sinf(omega);
    float Ar = decay * cr, Ai = decay * ci;
    float pr = 1.f, pi = 0.f;
    #pragma unroll 1
    for (int t = 0; t < TAPS; t++) {
        g_w[t*FF + f]           = pr*cr - pi*ci;
        g_w[TAPS*FF + t*FF + f] = pr*ci + pi*cr;
        float nr = pr*Ar - pi*Ai, ni = pr*Ai + pi*Ar;
        pr = nr; pi = ni;
    }
}

// ---------------- weight split ----------------
__global__ void wsplit_kernel(const float* __restrict__ w,
                              __half* __restrict__ h, __half* __restrict__ l, int n){
    int i = blockIdx.x*256 + threadIdx.x;
    if (i < n) { __half hi, lo; split2h(w[i], hi, lo); h[i] = hi; l[i] = lo; }
}

// ---------------- LayerNorm over D=1024 ----------------
template<bool SPLIT>
__global__ void ln_kernel(const float* __restrict__ x, const float* __restrict__ g,
                          const float* __restrict__ b, float* __restrict__ outf,
                          __half* __restrict__ oh, __half* __restrict__ ol) {
    __shared__ float red[8];
    int row = blockIdx.x, tid = threadIdx.x;
    float4 v = ((const float4*)(x + (size_t)row*DM))[tid];
    float mu = block_sum<8>(v.x + v.y + v.z + v.w, red) * (1.f/DM);
    float dx = v.x - mu, dy = v.y - mu, dz = v.z - mu, dw = v.w - mu;
    float var = block_sum<8>(dx*dx + dy*dy + dz*dz + dw*dw, red) * (1.f/DM);
    float rs = rsqrtf(var + LN_EPS);
    float4 gv = ((const float4*)g)[tid];
    float4 bv = ((const float4*)b)[tid];
    float o0 = dx*rs*gv.x + bv.x, o1 = dy*rs*gv.y + bv.y;
    float o2 = dz*rs*gv.z + bv.z, o3 = dw*rs*gv.w + bv.w;
    if (SPLIT) {
        __half h0,l0,h1,l1,h2,l2,h3,l3;
        split2h(o0,h0,l0); split2h(o1,h1,l1); split2h(o2,h2,l2); split2h(o3,h3,l3);
        size_t base = (size_t)row*DM + tid*4;
        ((__half2*)(oh+base))[0] = __halves2half2(h0,h1);
        ((__half2*)(oh+base))[1] = __halves2half2(h2,h3);
        ((__half2*)(ol+base))[0] = __halves2half2(l0,l1);
        ((__half2*)(ol+base))[1] = __halves2half2(l2,l3);
    } else {
        ((float4*)(outf + (size_t)row*DM))[tid] = make_float4(o0,o1,o2,o3);
    }
}

// ---------------- HMMA fp16 split GEMM: C[M,N] = A[M,K] * B[N,K]^T ---------
// hi pass f32-accum; two lo passes share one f16 accumulator (operands x2048).
// tile 128x128x32, 256 threads, 8 warps, warp tile 64x32.
// 3-stage cp.async pipeline, ONE __syncthreads per chunk.
#define ROWB 80u
#define TILEB (128u*ROWB)      /* 10240 */
#define STAGE (4u*TILEB)       /* 40960 */
#define NSTG  3

template<bool BIAS, bool GELU, bool SPLIT, bool ERR>
__global__ void __launch_bounds__(256, 1) gemm_mma(
    const __half* __restrict__ Ah, const __half* __restrict__ Al,
    const __half* __restrict__ Bh, const __half* __restrict__ Bl,
    const float* __restrict__ bias,
    float* __restrict__ Cf, __half* __restrict__ Ch, __half* __restrict__ Cl,
    const float* __restrict__ td, const float* __restrict__ ew,
    int M, int N, int K)
{
    extern __shared__ char dsm[];
    __shared__ float red[8];
    const uint32_t sb = smem_u32(dsm);
    const uint32_t OAH = 0, OAL = TILEB, OBH = 2*TILEB, OBL = 3*TILEB;

    const int m0 = blockIdx.y * 128, n0 = blockIdx.x * 128;
    const int tid = threadIdx.x, lane = tid & 31, wid = tid >> 5;
    const int wm0 = (wid & 1) * 64, wn0 = (wid >> 1) * 32;
    const int NC = K >> 5;

    float    acc[4][4][4];
    uint32_t a16[4][4][2];
    #pragma unroll
    for (int i = 0; i < 4; i++)
        #pragma unroll
        for (int j = 0; j < 4; j++) {
            #pragma unroll
            for (int r = 0; r < 4; r++) acc[i][j][r] = 0.f;
            a16[i][j][0] = 0u; a16[i][j][1] = 0u;
        }

    // cp.async: two 16B granules per thread per tile (256 thr, 512 granules)
    const int lr = tid >> 2, lg = tid & 3;

    auto load_stage = [&](int slot, int c){
        uint32_t s0 = sb + (uint32_t)slot*STAGE;
        size_t gb = (size_t)c * 64;           // 32 halfs = 64 bytes
        #pragma unroll
        for (int l = 0; l < 2; l++) {
            int r = lr + l*64;
            uint32_t d = s0 + (uint32_t)r*ROWB + (uint32_t)lg*16u;
            CPA16(d + OAH, (const char*)(Ah + (size_t)(m0 + r)*K + lg*8) + gb);
            CPA16(d + OAL, (const char*)(Al + (size_t)(m0 + r)*K + lg*8) + gb);
            CPA16(d + OBH, (const char*)(Bh + (size_t)(n0 + r)*K + lg*8) + gb);
            CPA16(d + OBL, (const char*)(Bl + (size_t)(n0 + r)*K + lg*8) + gb);
        }
        CPA_COMMIT();
    };

    const uint32_t a_row = (uint32_t)(wm0 + (lane & 15));
    const uint32_t a_kg  = (uint32_t)(lane >> 4);
    const uint32_t b_sel = (uint32_t)(lane >> 3);
    const uint32_t b_row = (uint32_t)(wn0 + ((b_sel >> 1) << 3) + (lane & 7));
    const uint32_t b_kg  = b_sel & 1u;

    load_stage(0, 0);
    load_stage(1, 1);
    int cs = 0, ls = 2;
    for (int c = 0; c < NC; c++) {
        if (c < NC - 1) CPA_WAIT1(); else CPA_WAIT0();
        __syncthreads();                       // all warps done with chunk c-1
        if (c + 2 < NC) {                      // slot ls == (c-1)%3, now free
            load_stage(ls, c + 2);
            ls = (ls == 2) ? 0 : ls + 1;
        }
        uint32_t s0 = sb + (uint32_t)cs*STAGE;
        cs = (cs == 2) ? 0 : cs + 1;

        #pragma unroll
        for (int s = 0; s < 2; s++) {          // two k16 steps per chunk
            uint32_t ah[4][4], al[4][4], bh[4][2], bl[4][2];
            #pragma unroll
            for (int mi = 0; mi < 4; mi++) {
                uint32_t ad = s0 + (a_row + mi*16u)*ROWB + ((uint32_t)s*2u + a_kg)*16u;
                LDSM_X4(ah[mi][0], ah[mi][1], ah[mi][2], ah[mi][3], ad + OAH);
                LDSM_X4(al[mi][0], al[mi][1], al[mi][2], al[mi][3], ad + OAL);
            }
            #pragma unroll
            for (int nj = 0; nj < 4; nj += 2) {
                uint32_t bd = s0 + (b_row + (uint32_t)nj*8u)*ROWB + ((uint32_t)s*2u + b_kg)*16u;
                LDSM_X4(bh[nj][0], bh[nj][1], bh[nj+1][0], bh[nj+1][1], bd + OBH);
                LDSM_X4(bl[nj][0], bl[nj][1], bl[nj+1][0], bl[nj+1][1], bd + OBL);
            }
            #pragma unroll
            for (int mi = 0; mi < 4; mi++)
                #pragma unroll
                for (int ni = 0; ni < 4; ni++) {
                    MMA_F32(acc[mi][ni], ah[mi], bh[ni]);
                    MMA_F16(a16[mi][ni], al[mi], bh[ni]);
                    MMA_F16(a16[mi][ni], ah[mi], bl[ni]);
                }
        }
    }

    float sw = 0.f;
    if (ERR) sw = 1.f / (1.f + expf(-ew[0]));
    float esum = 0.f;

    const int er = lane >> 2, ec = (lane & 3) * 2;
    #pragma unroll
    for (int mi = 0; mi < 4; mi++) {
        #pragma unroll
        for (int half = 0; half < 2; half++) {
            int m = m0 + wm0 + mi*16 + er + half*8;
            #pragma unroll
            for (int ni = 0; ni < 4; ni++) {
                int n = n0 + wn0 + ni*8 + ec;
                float2 lo = __half22float2(*(__half2*)&a16[mi][ni][half]);
                float v0 = acc[mi][ni][half*2 + 0] + lo.x * LO_INV;
                float v1 = acc[mi][ni][half*2 + 1] + lo.y * LO_INV;
                if (BIAS) { v0 += __ldg(&bias[n]); v1 += __ldg(&bias[n+1]); }
                if (GELU) {
                    v0 = 0.5f * v0 * (1.f + erff(v0 * 0.70710678118654752f));
                    v1 = 0.5f * v1 * (1.f + erff(v1 * 0.70710678118654752f));
                }
                if (ERR) {
                    float2 t = *(const float2*)(td + (size_t)m*N + n);
                    float e0 = fminf(fmaxf(v0 - t.x, -1.f), 1.f);
                    float e1 = fminf(fmaxf(v1 - t.y, -1.f), 1.f);
                    esum += e0*e0 + e1*e1;
                    v0 -= sw*e0; v1 -= sw*e1;
                }
                if (ERR || !SPLIT)
                    *(float2*)(Cf + (size_t)m*N + n) = make_float2(v0, v1);
                if (SPLIT) {
                    __half h0,l0,h1,l1;
                    split2h(v0,h0,l0); split2h(v1,h1,l1);
                    *(__half2*)(Ch + (size_t)m*N + n) = __halves2half2(h0,h1);
                    *(__half2*)(Cl + (size_t)m*N + n) = __halves2half2(l0,l1);
                }
            }
        }
    }
    if (ERR) {
        float s = block_sum<8>(esum, red);
        if (tid == 0) g_errpart[blockIdx.y * gridDim.x + blockIdx.x] = s;
    }
}

// ---------------- 32-tap complex causal FIR along S (fp16-split output) ----
// tile 32 t x 32 f, 256 threads, 4 outputs/thread.
__global__ void __launch_bounds__(256) conv_kernel(
    const float* __restrict__ u, __half* __restrict__ yh, __half* __restrict__ yl) {
    __shared__ float sur[63*32], sui[63*32];
    __shared__ float swr[TAPS*32], swi[TAPS*32];
    const int f0 = blockIdx.x * 32;
    const int t0 = blockIdx.y * 32;
    const int b  = blockIdx.z;
    const int tid = threadIdx.x;

    for (int i = tid; i < 63*32; i += 256) {
        int tt = i >> 5, fl = i & 31;
        int tg = t0 - 31 + tt;
        float vr = 0.f, vi = 0.f;
        if (tg >= 0) {
            size_t base = ((size_t)(b*SEQ + tg))*(2*FF) + f0 + fl;
            vr = u[base]; vi = u[base + FF];
        }
        sur[i] = vr; sui[i] = vi;
    }
    for (int i = tid; i < TAPS*32; i += 256) {
        int tt = i >> 5, fl = i & 31;
        swr[i] = g_w[tt*FF + f0 + fl];
        swi[i] = g_w[TAPS*FF + tt*FF + f0 + fl];
    }
    __syncthreads();

    const int fl = tid & 31, tr = tid >> 5;
    #pragma unroll
    for (int j = 0; j < 4; j++) {
        int tl = tr*4 + j;
        float ar = 0.f, ai = 0.f;
        #pragma unroll
        for (int t = 0; t < TAPS; t++) {
            int idx = (31 + tl - t)*32 + fl;
            float ur = sur[idx], ui = sui[idx];
            float wr = swr[t*32 + fl], wi = swi[t*32 + fl];
            ar += ur*wr - ui*wi;
            ai += ur*wi + ui*wr;
        }
        size_t ob = ((size_t)(b*SEQ + t0 + tl))*(2*FF) + f0 + fl;
        __half h, l;
        split2h(ar, h, l); yh[ob] = h;      yl[ob] = l;
        split2h(ai, h, l); yh[ob + FF] = h; yl[ob + FF] = l;
    }
}

__global__ void fin_kernel(float* __restrict__ out_scalar) {
    __shared__ float red[8];
    float s = 0.f;
    for (int i = threadIdx.x; i < 1024; i += 256) s += g_errpart[i];
    s = block_sum<8>(s, red);
    if (threadIdx.x == 0) {
        float pe = s / (float)((size_t)ROWS * DM);
        out_scalar[0] = fminf(fmaxf(pe, 0.f), 1.f);
    }
}

// ---------------- launch ----------------
extern "C" void kernel_launch(void* const* d_in, const int* in_sizes, int n_in,
                              void* d_out, int out_size) {
    const float* bu    = (const float*)d_in[0];
    const float* td    = (const float*)d_in[1];
    const float* Wspec = (const float*)d_in[2];
    const float* ldec  = (const float*)d_in[3];
    const float* freq  = (const float*)d_in[4];
    const float* Wfrom = (const float*)d_in[5];
    const float* l1g   = (const float*)d_in[6];
    const float* l1b   = (const float*)d_in[7];
    const float* W1    = (const float*)d_in[8];
    const float* b1    = (const float*)d_in[9];
    const float* W2    = (const float*)d_in[10];
    const float* b2    = (const float*)d_in[11];
    const float* l2g   = (const float*)d_in[12];
    const float* l2b   = (const float*)d_in[13];
    const float* ew    = (const float*)d_in[14];

    float* out       = (float*)d_out;
    float* corrected = out;
    float* nextpred  = out + (size_t)ROWS*DM;
    float* pe        = out + 2*(size_t)ROWS*DM;

    float *spec, *h2;
    __half *xh,*xl,*yh,*yl,*ch,*cl,*hh,*hl;
    __half *wsh,*wsl,*wfh,*wfl,*w1h,*w1l,*w2h,*w2l;
    cudaGetSymbolAddress((void**)&spec,   g_spec);
    cudaGetSymbolAddress((void**)&h2,     g_h2);
    cudaGetSymbolAddress((void**)&xh, g_xh); cudaGetSymbolAddress((void**)&xl, g_xl);
    cudaGetSymbolAddress((void**)&yh, g_yh); cudaGetSymbolAddress((void**)&yl, g_yl);
    cudaGetSymbolAddress((void**)&ch, g_ch); cudaGetSymbolAddress((void**)&cl, g_cl);
    cudaGetSymbolAddress((void**)&hh, g_hh); cudaGetSymbolAddress((void**)&hl, g_hl);
    cudaGetSymbolAddress((void**)&wsh, g_wsh); cudaGetSymbolAddress((void**)&wsl, g_wsl);
    cudaGetSymbolAddress((void**)&wfh, g_wfh); cudaGetSymbolAddress((void**)&wfl, g_wfl);
    cudaGetSymbolAddress((void**)&w1h, g_w1h); cudaGetSymbolAddress((void**)&w1l, g_w1l);
    cudaGetSymbolAddress((void**)&w2h, g_w2h); cudaGetSymbolAddress((void**)&w2l, g_w2l);

    const int SMEM_BYTES = NSTG * (int)STAGE;   // 122880
    cudaFuncSetAttribute(gemm_mma<false,false,false,false>, cudaFuncAttributeMaxDynamicSharedMemorySize, SMEM_BYTES);
    cudaFuncSetAttribute(gemm_mma<false,false,true ,true >, cudaFuncAttributeMaxDynamicSharedMemorySize, SMEM_BYTES);
    cudaFuncSetAttribute(gemm_mma<true ,true ,true ,false>, cudaFuncAttributeMaxDynamicSharedMemorySize, SMEM_BYTES);
    cudaFuncSetAttribute(gemm_mma<true ,false,false,false>, cudaFuncAttributeMaxDynamicSharedMemorySize, SMEM_BYTES);

    prep_kernel<<<1, 256>>>(ldec, freq);
    wsplit_kernel<<<(2*FF*DM+255)/256, 256>>>(Wspec, wsh, wsl, 2*FF*DM);
    wsplit_kernel<<<(DM*2*FF+255)/256, 256>>>(Wfrom, wfh, wfl, DM*2*FF);
    wsplit_kernel<<<(DM*DM+255)/256, 256>>>(W1, w1h, w1l, DM*DM);
    wsplit_kernel<<<(DM*DM+255)/256, 256>>>(W2, w2h, w2l, DM*DM);

    ln_kernel<true><<<ROWS, 256>>>(bu, l1g, l1b, nullptr, xh, xl);

    gemm_mma<false,false,false,false><<<dim3((2*FF)/128, ROWS/128), 256, SMEM_BYTES>>>(
        xh, xl, wsh, wsl, nullptr, spec, nullptr, nullptr, nullptr, nullptr, ROWS, 2*FF, DM);

    conv_kernel<<<dim3(FF/32, SEQ/32, BSZ), 256>>>(spec, yh, yl);

    // GEMM2 fused with error/corrected/split + per-block error sums
    gemm_mma<false,false,true,true><<<dim3(DM/128, ROWS/128), 256, SMEM_BYTES>>>(
        yh, yl, wfh, wfl, nullptr, corrected, ch, cl, td, ew, ROWS, DM, 2*FF);

    fin_kernel<<<1, 256>>>(pe);

    gemm_mma<true,true,true,false><<<dim3(DM/128, ROWS/128), 256, SMEM_BYTES>>>(
        ch, cl, w1h, w1l, b1, nullptr, hh, hl, nullptr, nullptr, ROWS, DM, DM);

    gemm_mma<true,false,false,false><<<dim3(DM/128, ROWS/128), 256, SMEM_BYTES>>>(
        hh, hl, w2h, w2l, b2, h2, nullptr, nullptr, nullptr, nullptr, ROWS, DM, DM);

    ln_kernel<false><<<ROWS, 256>>>(h2, l2g, l2b, nextpred, nullptr, nullptr);
}

// round 7
// speedup vs baseline: 2.7145x; 1.2661x over previous
#include <cuda_runtime.h>
#include <cuda_fp16.h>
#include <math.h>
#include <stdint.h>

#define BSZ  4
#define SEQ  4096
#define DM   1024
#define FF   256
#define ROWS (BSZ*SEQ)            /* 16384 */
#define TAPS 32
#define LN_EPS 1e-5f
#define LO_S   2048.0f
#define LO_INV 4.8828125e-4f

// ---------------- scratch (device globals: no alloc allowed) ----------------
__device__ float g_spec  [(size_t)ROWS*2*FF];   // fp32 GEMM1 out (conv input)
__device__ float g_h2    [(size_t)ROWS*DM];     // fp32 GEMM4 out
__device__ __half g_xh[(size_t)ROWS*DM],  g_xl[(size_t)ROWS*DM];
__device__ __half g_yh[(size_t)ROWS*2*FF],g_yl[(size_t)ROWS*2*FF];
__device__ __half g_ch[(size_t)ROWS*DM],  g_cl[(size_t)ROWS*DM];
__device__ __half g_hh[(size_t)ROWS*DM],  g_hl[(size_t)ROWS*DM];
__device__ __half g_wsh[2*FF*DM];
__device__ __half g_wfh[DM*2*FF];
__device__ __half g_w1h[DM*DM];
__device__ __half g_w2h[DM*DM];
__device__ float g_w[2*TAPS*FF];
__device__ float g_errpart[1024];

// ---------------- PTX helpers ----------------
__device__ __forceinline__ uint32_t smem_u32(const void* p){
    uint32_t a; asm("{ .reg .u64 t; cvta.to.shared.u64 t, %1; cvt.u32.u64 %0, t; }":"=r"(a):"l"(p)); return a;
}
#define CPA16(dst,src) asm volatile("cp.async.cg.shared.global [%0],[%1],16;"::"r"(dst),"l"(src))
#define CPA_COMMIT()   asm volatile("cp.async.commit_group;":::"memory")
#define CPA_WAIT2()    asm volatile("cp.async.wait_group 2;":::"memory")
#define CPA_WAIT1()    asm volatile("cp.async.wait_group 1;":::"memory")
#define CPA_WAIT0()    asm volatile("cp.async.wait_group 0;":::"memory")

#define LDSM_X4(r0,r1,r2,r3,addr) \
    asm volatile("ldmatrix.sync.aligned.m8n8.x4.shared.b16 {%0,%1,%2,%3},[%4];" \
        : "=r"(r0),"=r"(r1),"=r"(r2),"=r"(r3) : "r"(addr))

#define MMA_F32(d,a,b) \
    asm volatile("mma.sync.aligned.m16n8k16.row.col.f32.f16.f16.f32 " \
        "{%0,%1,%2,%3},{%4,%5,%6,%7},{%8,%9},{%0,%1,%2,%3};" \
        : "+f"((d)[0]),"+f"((d)[1]),"+f"((d)[2]),"+f"((d)[3]) \
        : "r"((a)[0]),"r"((a)[1]),"r"((a)[2]),"r"((a)[3]),"r"((b)[0]),"r"((b)[1]))

#define MMA_F16(d,a,b) \
    asm volatile("mma.sync.aligned.m16n8k16.row.col.f16.f16.f16.f16 " \
        "{%0,%1},{%2,%3,%4,%5},{%6,%7},{%0,%1};" \
        : "+r"((d)[0]),"+r"((d)[1]) \
        : "r"((a)[0]),"r"((a)[1]),"r"((a)[2]),"r"((a)[3]),"r"((b)[0]),"r"((b)[1]))

__device__ __forceinline__ void split2h(float v, __half& h, __half& l){
    h = __float2half(v);
    l = __float2half((v - __half2float(h)) * LO_S);
}

// ---------------- block reduce ----------------
template<int WARPS>
__device__ __forceinline__ float block_sum(float v, float* red) {
    #pragma unroll
    for (int o = 16; o > 0; o >>= 1) v += __shfl_xor_sync(0xffffffffu, v, o);
    int lane = threadIdx.x & 31, w = threadIdx.x >> 5;
    if (lane == 0) red[w] = v;
    __syncthreads();
    if (w == 0) {
        float r = (lane < WARPS) ? red[lane] : 0.f;
        #pragma unroll
        for (int o = 16; o > 0; o >>= 1) r += __shfl_xor_sync(0xffffffffu, r, o);
        if (lane == 0) red[0] = r;
    }
    __syncthreads();
    float out = red[0];
    __syncthreads();
    return out;
}

// ---------------- FIR tap precompute ----------------
__global__ void prep_kernel(const float* __restrict__ log_decay,
                            const float* __restrict__ freq) {
    int f = threadIdx.x;
    float decay = 1.f / (1.f + expf(-log_decay[f]));
    float omega = tanhf(freq[f]) * 0.1f;
    float cr = cosf(omega), ci = sinf(omega);
    float Ar = decay * cr, Ai = decay * ci;
    float pr = 1.f, pi = 0.f;
    #pragma unroll 1
    for (int t = 0; t < TAPS; t++) {
        g_w[t*FF + f]           = pr*cr - pi*ci;
        g_w[TAPS*FF + t*FF + f] = pr*ci + pi*cr;
        float nr = pr*Ar - pi*Ai, ni = pr*Ai + pi*Ar;
        pr = nr; pi = ni;
    }
}

// ---------------- weight to fp16 (hi only — lo term dropped) ----------------
__global__ void wsplit_kernel(const float* __restrict__ w,
                              __half* __restrict__ h, int n){
    int i = blockIdx.x*256 + threadIdx.x;
    if (i < n) h[i] = __float2half(w[i]);
}

// ---------------- LayerNorm over D=1024 ----------------
template<bool SPLIT>
__global__ void ln_kernel(const float* __restrict__ x, const float* __restrict__ g,
                          const float* __restrict__ b, float* __restrict__ outf,
                          __half* __restrict__ oh, __half* __restrict__ ol) {
    __shared__ float red[8];
    int row = blockIdx.x, tid = threadIdx.x;
    float4 v = ((const float4*)(x + (size_t)row*DM))[tid];
    float mu = block_sum<8>(v.x + v.y + v.z + v.w, red) * (1.f/DM);
    float dx = v.x - mu, dy = v.y - mu, dz = v.z - mu, dw = v.w - mu;
    float var = block_sum<8>(dx*dx + dy*dy + dz*dz + dw*dw, red) * (1.f/DM);
    float rs = rsqrtf(var + LN_EPS);
    float4 gv = ((const float4*)g)[tid];
    float4 bv = ((const float4*)b)[tid];
    float o0 = dx*rs*gv.x + bv.x, o1 = dy*rs*gv.y + bv.y;
    float o2 = dz*rs*gv.z + bv.z, o3 = dw*rs*gv.w + bv.w;
    if (SPLIT) {
        __half h0,l0,h1,l1,h2,l2,h3,l3;
        split2h(o0,h0,l0); split2h(o1,h1,l1); split2h(o2,h2,l2); split2h(o3,h3,l3);
        size_t base = (size_t)row*DM + tid*4;
        ((__half2*)(oh+base))[0] = __halves2half2(h0,h1);
        ((__half2*)(oh+base))[1] = __halves2half2(h2,h3);
        ((__half2*)(ol+base))[0] = __halves2half2(l0,l1);
        ((__half2*)(ol+base))[1] = __halves2half2(l2,l3);
    } else {
        ((float4*)(outf + (size_t)row*DM))[tid] = make_float4(o0,o1,o2,o3);
    }
}

// ---------------- HMMA fp16 2-pass GEMM: C[M,N] = A[M,K] * B[N,K]^T --------
// C ~= Ah*Bh (f32 accum) + Al*Bh (f16 accum, Al prescaled x2048).
// tile 128x128x32, 256 threads, 8 warps, warp tile 64x32.
// 4-stage cp.async pipeline (3 chunks in flight), ONE __syncthreads per chunk.
#define ROWB 80u
#define TILEB (128u*ROWB)      /* 10240 */
#define STAGE (3u*TILEB)       /* 30720: Ah, Al, Bh */
#define NSTG  4

template<bool BIAS, bool GELU, bool SPLIT, bool ERR>
__global__ void __launch_bounds__(256, 1) gemm_mma(
    const __half* __restrict__ Ah, const __half* __restrict__ Al,
    const __half* __restrict__ Bh,
    const float* __restrict__ bias,
    float* __restrict__ Cf, __half* __restrict__ Ch, __half* __restrict__ Cl,
    const float* __restrict__ td, const float* __restrict__ ew,
    int M, int N, int K)
{
    extern __shared__ char dsm[];
    __shared__ float red[8];
    const uint32_t sb = smem_u32(dsm);
    const uint32_t OAH = 0, OAL = TILEB, OBH = 2*TILEB;

    const int m0 = blockIdx.y * 128, n0 = blockIdx.x * 128;
    const int tid = threadIdx.x, lane = tid & 31, wid = tid >> 5;
    const int wm0 = (wid & 1) * 64, wn0 = (wid >> 1) * 32;
    const int NC = K >> 5;

    float    acc[4][4][4];
    uint32_t a16[4][4][2];
    #pragma unroll
    for (int i = 0; i < 4; i++)
        #pragma unroll
        for (int j = 0; j < 4; j++) {
            #pragma unroll
            for (int r = 0; r < 4; r++) acc[i][j][r] = 0.f;
            a16[i][j][0] = 0u; a16[i][j][1] = 0u;
        }

    const int lr = tid >> 2, lg = tid & 3;

    auto load_stage = [&](int slot, int c){
        uint32_t s0 = sb + (uint32_t)slot*STAGE;
        size_t gb = (size_t)c * 64;           // 32 halfs = 64 bytes
        #pragma unroll
        for (int l = 0; l < 2; l++) {
            int r = lr + l*64;
            uint32_t d = s0 + (uint32_t)r*ROWB + (uint32_t)lg*16u;
            CPA16(d + OAH, (const char*)(Ah + (size_t)(m0 + r)*K + lg*8) + gb);
            CPA16(d + OAL, (const char*)(Al + (size_t)(m0 + r)*K + lg*8) + gb);
            CPA16(d + OBH, (const char*)(Bh + (size_t)(n0 + r)*K + lg*8) + gb);
        }
        CPA_COMMIT();
    };

    const uint32_t a_row = (uint32_t)(wm0 + (lane & 15));
    const uint32_t a_kg  = (uint32_t)(lane >> 4);
    const uint32_t b_sel = (uint32_t)(lane >> 3);
    const uint32_t b_row = (uint32_t)(wn0 + ((b_sel >> 1) << 3) + (lane & 7));
    const uint32_t b_kg  = b_sel & 1u;

    load_stage(0, 0);
    load_stage(1, 1);
    load_stage(2, 2);
    int cs = 0, ls = 3;
    for (int c = 0; c < NC; c++) {
        if (c < NC - 2)      CPA_WAIT2();
        else if (c < NC - 1) CPA_WAIT1();
        else                 CPA_WAIT0();
        __syncthreads();                       // all warps done with chunk c-1
        if (c + 3 < NC) {                      // slot ls == (c-1)&3, now free
            load_stage(ls, c + 3);
            ls = (ls + 1) & 3;
        }
        uint32_t s0 = sb + (uint32_t)cs*STAGE;
        cs = (cs + 1) & 3;

        #pragma unroll
        for (int s = 0; s < 2; s++) {          // two k16 steps per chunk
            uint32_t ah[4][4], al[4][4], bh[4][2];
            #pragma unroll
            for (int mi = 0; mi < 4; mi++) {
                uint32_t ad = s0 + (a_row + mi*16u)*ROWB + ((uint32_t)s*2u + a_kg)*16u;
                LDSM_X4(ah[mi][0], ah[mi][1], ah[mi][2], ah[mi][3], ad + OAH);
                LDSM_X4(al[mi][0], al[mi][1], al[mi][2], al[mi][3], ad + OAL);
            }
            #pragma unroll
            for (int nj = 0; nj < 4; nj += 2) {
                uint32_t bd = s0 + (b_row + (uint32_t)nj*8u)*ROWB + ((uint32_t)s*2u + b_kg)*16u;
                LDSM_X4(bh[nj][0], bh[nj][1], bh[nj+1][0], bh[nj+1][1], bd + OBH);
            }
            #pragma unroll
            for (int mi = 0; mi < 4; mi++)
                #pragma unroll
                for (int ni = 0; ni < 4; ni++) {
                    MMA_F32(acc[mi][ni], ah[mi], bh[ni]);
                    MMA_F16(a16[mi][ni], al[mi], bh[ni]);
                }
        }
    }

    float sw = 0.f;
    if (ERR) sw = 1.f / (1.f + expf(-ew[0]));
    float esum = 0.f;

    const int er = lane >> 2, ec = (lane & 3) * 2;
    #pragma unroll
    for (int mi = 0; mi < 4; mi++) {
        #pragma unroll
        for (int half = 0; half < 2; half++) {
            int m = m0 + wm0 + mi*16 + er + half*8;
            #pragma unroll
            for (int ni = 0; ni < 4; ni++) {
                int n = n0 + wn0 + ni*8 + ec;
                float2 lo = __half22float2(*(__half2*)&a16[mi][ni][half]);
                float v0 = acc[mi][ni][half*2 + 0] + lo.x * LO_INV;
                float v1 = acc[mi][ni][half*2 + 1] + lo.y * LO_INV;
                if (BIAS) { v0 += __ldg(&bias[n]); v1 += __ldg(&bias[n+1]); }
                if (GELU) {
                    v0 = 0.5f * v0 * (1.f + erff(v0 * 0.70710678118654752f));
                    v1 = 0.5f * v1 * (1.f + erff(v1 * 0.70710678118654752f));
                }
                if (ERR) {
                    float2 t = *(const float2*)(td + (size_t)m*N + n);
                    float e0 = fminf(fmaxf(v0 - t.x, -1.f), 1.f);
                    float e1 = fminf(fmaxf(v1 - t.y, -1.f), 1.f);
                    esum += e0*e0 + e1*e1;
                    v0 -= sw*e0; v1 -= sw*e1;
                }
                if (ERR || !SPLIT)
                    *(float2*)(Cf + (size_t)m*N + n) = make_float2(v0, v1);
                if (SPLIT) {
                    __half h0,l0,h1,l1;
                    split2h(v0,h0,l0); split2h(v1,h1,l1);
                    *(__half2*)(Ch + (size_t)m*N + n) = __halves2half2(h0,h1);
                    *(__half2*)(Cl + (size_t)m*N + n) = __halves2half2(l0,l1);
                }
            }
        }
    }
    if (ERR) {
        float s = block_sum<8>(esum, red);
        if (tid == 0) g_errpart[blockIdx.y * gridDim.x + blockIdx.x] = s;
    }
}

// ---------------- 32-tap complex causal FIR along S (fp16-split output) ----
__global__ void __launch_bounds__(256) conv_kernel(
    const float* __restrict__ u, __half* __restrict__ yh, __half* __restrict__ yl) {
    __shared__ float sur[63*32], sui[63*32];
    __shared__ float swr[TAPS*32], swi[TAPS*32];
    const int f0 = blockIdx.x * 32;
    const int t0 = blockIdx.y * 32;
    const int b  = blockIdx.z;
    const int tid = threadIdx.x;

    for (int i = tid; i < 63*32; i += 256) {
        int tt = i >> 5, fl = i & 31;
        int tg = t0 - 31 + tt;
        float vr = 0.f, vi = 0.f;
        if (tg >= 0) {
            size_t base = ((size_t)(b*SEQ + tg))*(2*FF) + f0 + fl;
            vr = u[base]; vi = u[base + FF];
        }
        sur[i] = vr; sui[i] = vi;
    }
    for (int i = tid; i < TAPS*32; i += 256) {
        int tt = i >> 5, fl = i & 31;
        swr[i] = g_w[tt*FF + f0 + fl];
        swi[i] = g_w[TAPS*FF + tt*FF + f0 + fl];
    }
    __syncthreads();

    const int fl = tid & 31, tr = tid >> 5;
    #pragma unroll
    for (int j = 0; j < 4; j++) {
        int tl = tr*4 + j;
        float ar = 0.f, ai = 0.f;
        #pragma unroll
        for (int t = 0; t < TAPS; t++) {
            int idx = (31 + tl - t)*32 + fl;
            float ur = sur[idx], ui = sui[idx];
            float wr = swr[t*32 + fl], wi = swi[t*32 + fl];
            ar += ur*wr - ui*wi;
            ai += ur*wi + ui*wr;
        }
        size_t ob = ((size_t)(b*SEQ + t0 + tl))*(2*FF) + f0 + fl;
        __half h, l;
        split2h(ar, h, l); yh[ob] = h;      yl[ob] = l;
        split2h(ai, h, l); yh[ob + FF] = h; yl[ob + FF] = l;
    }
}

__global__ void fin_kernel(float* __restrict__ out_scalar) {
    __shared__ float red[8];
    float s = 0.f;
    for (int i = threadIdx.x; i < 1024; i += 256) s += g_errpart[i];
    s = block_sum<8>(s, red);
    if (threadIdx.x == 0) {
        float pe = s / (float)((size_t)ROWS * DM);
        out_scalar[0] = fminf(fmaxf(pe, 0.f), 1.f);
    }
}

// ---------------- launch ----------------
extern "C" void kernel_launch(void* const* d_in, const int* in_sizes, int n_in,
                              void* d_out, int out_size) {
    const float* bu    = (const float*)d_in[0];
    const float* td    = (const float*)d_in[1];
    const float* Wspec = (const float*)d_in[2];
    const float* ldec  = (const float*)d_in[3];
    const float* freq  = (const float*)d_in[4];
    const float* Wfrom = (const float*)d_in[5];
    const float* l1g   = (const float*)d_in[6];
    const float* l1b   = (const float*)d_in[7];
    const float* W1    = (const float*)d_in[8];
    const float* b1    = (const float*)d_in[9];
    const float* W2    = (const float*)d_in[10];
    const float* b2    = (const float*)d_in[11];
    const float* l2g   = (const float*)d_in[12];
    const float* l2b   = (const float*)d_in[13];
    const float* ew    = (const float*)d_in[14];

    float* out       = (float*)d_out;
    float* corrected = out;
    float* nextpred  = out + (size_t)ROWS*DM;
    float* pe        = out + 2*(size_t)ROWS*DM;

    float *spec, *h2;
    __half *xh,*xl,*yh,*yl,*ch,*cl,*hh,*hl;
    __half *wsh,*wfh,*w1h,*w2h;
    cudaGetSymbolAddress((void**)&spec,   g_spec);
    cudaGetSymbolAddress((void**)&h2,     g_h2);
    cudaGetSymbolAddress((void**)&xh, g_xh); cudaGetSymbolAddress((void**)&xl, g_xl);
    cudaGetSymbolAddress((void**)&yh, g_yh); cudaGetSymbolAddress((void**)&yl, g_yl);
    cudaGetSymbolAddress((void**)&ch, g_ch); cudaGetSymbolAddress((void**)&cl, g_cl);
    cudaGetSymbolAddress((void**)&hh, g_hh); cudaGetSymbolAddress((void**)&hl, g_hl);
    cudaGetSymbolAddress((void**)&wsh, g_wsh);
    cudaGetSymbolAddress((void**)&wfh, g_wfh);
    cudaGetSymbolAddress((void**)&w1h, g_w1h);
    cudaGetSymbolAddress((void**)&w2h, g_w2h);

    const int SMEM_BYTES = NSTG * (int)STAGE;   // 122880
    cudaFuncSetAttribute(gemm_mma<false,false,false,false>, cudaFuncAttributeMaxDynamicSharedMemorySize, SMEM_BYTES);
    cudaFuncSetAttribute(gemm_mma<false,false,true ,true >, cudaFuncAttributeMaxDynamicSharedMemorySize, SMEM_BYTES);
    cudaFuncSetAttribute(gemm_mma<true ,true ,true ,false>, cudaFuncAttributeMaxDynamicSharedMemorySize, SMEM_BYTES);
    cudaFuncSetAttribute(gemm_mma<true ,false,false,false>, cudaFuncAttributeMaxDynamicSharedMemorySize, SMEM_BYTES);

    prep_kernel<<<1, 256>>>(ldec, freq);
    wsplit_kernel<<<(2*FF*DM+255)/256, 256>>>(Wspec, wsh, 2*FF*DM);
    wsplit_kernel<<<(DM*2*FF+255)/256, 256>>>(Wfrom, wfh, DM*2*FF);
    wsplit_kernel<<<(DM*DM+255)/256, 256>>>(W1, w1h, DM*DM);
    wsplit_kernel<<<(DM*DM+255)/256, 256>>>(W2, w2h, DM*DM);

    ln_kernel<true><<<ROWS, 256>>>(bu, l1g, l1b, nullptr, xh, xl);

    gemm_mma<false,false,false,false><<<dim3((2*FF)/128, ROWS/128), 256, SMEM_BYTES>>>(
        xh, xl, wsh, nullptr, spec, nullptr, nullptr, nullptr, nullptr, ROWS, 2*FF, DM);

    conv_kernel<<<dim3(FF/32, SEQ/32, BSZ), 256>>>(spec, yh, yl);

    // GEMM2 fused with error/corrected/split + per-block error sums
    gemm_mma<false,false,true,true><<<dim3(DM/128, ROWS/128), 256, SMEM_BYTES>>>(
        yh, yl, wfh, nullptr, corrected, ch, cl, td, ew, ROWS, DM, 2*FF);

    fin_kernel<<<1, 256>>>(pe);

    gemm_mma<true,true,true,false><<<dim3(DM/128, ROWS/128), 256, SMEM_BYTES>>>(
        ch, cl, w1h, b1, nullptr, hh, hl, nullptr, nullptr, ROWS, DM, DM);

    gemm_mma<true,false,false,false><<<dim3(DM/128, ROWS/128), 256, SMEM_BYTES>>>(
        hh, hl, w2h, b2, h2, nullptr, nullptr, nullptr, nullptr, ROWS, DM, DM);

    ln_kernel<false><<<ROWS, 256>>>(h2, l2g, l2b, nextpred, nullptr, nullptr);
}

// round 8
// speedup vs baseline: 3.0538x; 1.1250x over previous
#include <cuda_runtime.h>
#include <cuda_fp16.h>
#include <math.h>
#include <stdint.h>

#define BSZ  4
#define SEQ  4096
#define DM   1024
#define FF   256
#define ROWS (BSZ*SEQ)            /* 16384 */
#define TAPS 32
#define LN_EPS 1e-5f
#define LO_S   2048.0f
#define LO_INV 4.8828125e-4f

// ---------------- scratch (device globals: no alloc allowed) ----------------
__device__ float g_spec  [(size_t)ROWS*2*FF];   // fp32 GEMM1 out (conv input)
__device__ float g_h2    [(size_t)ROWS*DM];     // fp32 GEMM4 out
__device__ __half g_xh[(size_t)ROWS*DM],  g_xl[(size_t)ROWS*DM];
__device__ __half g_yh[(size_t)ROWS*2*FF],g_yl[(size_t)ROWS*2*FF];
__device__ __half g_ch[(size_t)ROWS*DM],  g_cl[(size_t)ROWS*DM];
__device__ __half g_hh[(size_t)ROWS*DM],  g_hl[(size_t)ROWS*DM];
__device__ __half g_wsh[2*FF*DM];
__device__ __half g_wfh[DM*2*FF];
__device__ __half g_w1h[DM*DM];
__device__ __half g_w2h[DM*DM];
__device__ float g_w[2*TAPS*FF];
__device__ float g_errpart[1024];

// ---------------- PTX helpers ----------------
__device__ __forceinline__ uint32_t smem_u32(const void* p){
    uint32_t a; asm("{ .reg .u64 t; cvta.to.shared.u64 t, %1; cvt.u32.u64 %0, t; }":"=r"(a):"l"(p)); return a;
}
#define CPA16(dst,src) asm volatile("cp.async.cg.shared.global [%0],[%1],16;"::"r"(dst),"l"(src))
#define CPA_COMMIT()   asm volatile("cp.async.commit_group;":::"memory")
#define CPA_WAIT2()    asm volatile("cp.async.wait_group 2;":::"memory")
#define CPA_WAIT1()    asm volatile("cp.async.wait_group 1;":::"memory")
#define CPA_WAIT0()    asm volatile("cp.async.wait_group 0;":::"memory")

#define LDSM_X4(r0,r1,r2,r3,addr) \
    asm volatile("ldmatrix.sync.aligned.m8n8.x4.shared.b16 {%0,%1,%2,%3},[%4];" \
        : "=r"(r0),"=r"(r1),"=r"(r2),"=r"(r3) : "r"(addr))

#define MMA_F32(d,a,b) \
    asm volatile("mma.sync.aligned.m16n8k16.row.col.f32.f16.f16.f32 " \
        "{%0,%1,%2,%3},{%4,%5,%6,%7},{%8,%9},{%0,%1,%2,%3};" \
        : "+f"((d)[0]),"+f"((d)[1]),"+f"((d)[2]),"+f"((d)[3]) \
        : "r"((a)[0]),"r"((a)[1]),"r"((a)[2]),"r"((a)[3]),"r"((b)[0]),"r"((b)[1]))

#define MMA_F16(d,a,b) \
    asm volatile("mma.sync.aligned.m16n8k16.row.col.f16.f16.f16.f16 " \
        "{%0,%1},{%2,%3,%4,%5},{%6,%7},{%0,%1};" \
        : "+r"((d)[0]),"+r"((d)[1]) \
        : "r"((a)[0]),"r"((a)[1]),"r"((a)[2]),"r"((a)[3]),"r"((b)[0]),"r"((b)[1]))

__device__ __forceinline__ void split2h(float v, __half& h, __half& l){
    h = __float2half(v);
    l = __float2half((v - __half2float(h)) * LO_S);
}

// ---------------- block reduce ----------------
template<int WARPS>
__device__ __forceinline__ float block_sum(float v, float* red) {
    #pragma unroll
    for (int o = 16; o > 0; o >>= 1) v += __shfl_xor_sync(0xffffffffu, v, o);
    int lane = threadIdx.x & 31, w = threadIdx.x >> 5;
    if (lane == 0) red[w] = v;
    __syncthreads();
    if (w == 0) {
        float r = (lane < WARPS) ? red[lane] : 0.f;
        #pragma unroll
        for (int o = 16; o > 0; o >>= 1) r += __shfl_xor_sync(0xffffffffu, r, o);
        if (lane == 0) red[0] = r;
    }
    __syncthreads();
    float out = red[0];
    __syncthreads();
    return out;
}

// ---------------- FIR tap precompute ----------------
__global__ void prep_kernel(const float* __restrict__ log_decay,
                            const float* __restrict__ freq) {
    int f = threadIdx.x;
    float decay = 1.f / (1.f + expf(-log_decay[f]));
    float omega = tanhf(freq[f]) * 0.1f;
    float cr = cosf(omega), ci = sinf(omega);
    float Ar = decay * cr, Ai = decay * ci;
    float pr = 1.f, pi = 0.f;
    #pragma unroll 1
    for (int t = 0; t < TAPS; t++) {
        g_w[t*FF + f]           = pr*cr - pi*ci;
        g_w[TAPS*FF + t*FF + f] = pr*ci + pi*cr;
        float nr = pr*Ar - pi*Ai, ni = pr*Ai + pi*Ar;
        pr = nr; pi = ni;
    }
}

// ---------------- all-weights to fp16 (single launch) ----------------------
#define NW1 (2*FF*DM)            /* 524288  */
#define NW2 (DM*2*FF)            /* 524288  */
#define NW3 (DM*DM)              /* 1048576 */
#define NW4 (DM*DM)              /* 1048576 */
__global__ void wsplit_all_kernel(const float* __restrict__ ws, const float* __restrict__ wf,
                                  const float* __restrict__ w1, const float* __restrict__ w2){
    int i = blockIdx.x*256 + threadIdx.x;
    if (i < NW1)                      g_wsh[i]                 = __float2half(ws[i]);
    else if (i < NW1+NW2)             g_wfh[i-NW1]             = __float2half(wf[i-NW1]);
    else if (i < NW1+NW2+NW3)         g_w1h[i-NW1-NW2]         = __float2half(w1[i-NW1-NW2]);
    else if (i < NW1+NW2+NW3+NW4)     g_w2h[i-NW1-NW2-NW3]     = __float2half(w2[i-NW1-NW2-NW3]);
}

// ---------------- LayerNorm over D=1024 ----------------
template<bool SPLIT>
__global__ void ln_kernel(const float* __restrict__ x, const float* __restrict__ g,
                          const float* __restrict__ b, float* __restrict__ outf,
                          __half* __restrict__ oh, __half* __restrict__ ol) {
    __shared__ float red[8];
    int row = blockIdx.x, tid = threadIdx.x;
    float4 v = ((const float4*)(x + (size_t)row*DM))[tid];
    float mu = block_sum<8>(v.x + v.y + v.z + v.w, red) * (1.f/DM);
    float dx = v.x - mu, dy = v.y - mu, dz = v.z - mu, dw = v.w - mu;
    float var = block_sum<8>(dx*dx + dy*dy + dz*dz + dw*dw, red) * (1.f/DM);
    float rs = rsqrtf(var + LN_EPS);
    float4 gv = ((const float4*)g)[tid];
    float4 bv = ((const float4*)b)[tid];
    float o0 = dx*rs*gv.x + bv.x, o1 = dy*rs*gv.y + bv.y;
    float o2 = dz*rs*gv.z + bv.z, o3 = dw*rs*gv.w + bv.w;
    if (SPLIT) {
        __half h0,l0,h1,l1,h2,l2,h3,l3;
        split2h(o0,h0,l0); split2h(o1,h1,l1); split2h(o2,h2,l2); split2h(o3,h3,l3);
        size_t base = (size_t)row*DM + tid*4;
        ((__half2*)(oh+base))[0] = __halves2half2(h0,h1);
        ((__half2*)(oh+base))[1] = __halves2half2(h2,h3);
        ((__half2*)(ol+base))[0] = __halves2half2(l0,l1);
        ((__half2*)(ol+base))[1] = __halves2half2(l2,l3);
    } else {
        ((float4*)(outf + (size_t)row*DM))[tid] = make_float4(o0,o1,o2,o3);
    }
}

// ---------------- HMMA fp16 2-pass GEMM: C[M,N] = A[M,K] * B[N,K]^T --------
// C ~= Ah*Bh (f32 accum) + Al*Bh (f16 accum, Al prescaled x2048).
// tile 128x128x64, 256 threads, 8 warps, warp tile 64x32.
// 4-stage cp.async pipeline (3 chunks in flight), ONE __syncthreads per chunk.
#define ROWB 144u              /* 128B data + 16B pad; 9 mod 8 = 1 rotation */
#define TILEB (128u*ROWB)      /* 18432 */
#define STAGE (3u*TILEB)       /* 55296: Ah, Al, Bh */
#define NSTG  4                /* 221184 B total */

template<bool BIAS, bool GELU, bool SPLIT, bool ERR>
__global__ void __launch_bounds__(256, 1) gemm_mma(
    const __half* __restrict__ Ah, const __half* __restrict__ Al,
    const __half* __restrict__ Bh,
    const float* __restrict__ bias,
    float* __restrict__ Cf, __half* __restrict__ Ch, __half* __restrict__ Cl,
    const float* __restrict__ td, const float* __restrict__ ew,
    int M, int N, int K)
{
    extern __shared__ char dsm[];
    __shared__ float red[8];
    const uint32_t sb = smem_u32(dsm);
    const uint32_t OAH = 0, OAL = TILEB, OBH = 2*TILEB;

    const int m0 = blockIdx.y * 128, n0 = blockIdx.x * 128;
    const int tid = threadIdx.x, lane = tid & 31, wid = tid >> 5;
    const int wm0 = (wid & 1) * 64, wn0 = (wid >> 1) * 32;
    const int NC = K >> 6;                 // 64-K chunks

    float    acc[4][4][4];
    uint32_t a16[4][4][2];
    #pragma unroll
    for (int i = 0; i < 4; i++)
        #pragma unroll
        for (int j = 0; j < 4; j++) {
            #pragma unroll
            for (int r = 0; r < 4; r++) acc[i][j][r] = 0.f;
            a16[i][j][0] = 0u; a16[i][j][1] = 0u;
        }

    // cp.async: 128 rows x 8 granules(16B) per tile; 256 thr -> 4 rows groups
    const int lr = tid >> 3, lg = tid & 7;

    auto load_stage = [&](int slot, int c){
        uint32_t s0 = sb + (uint32_t)slot*STAGE;
        size_t gb = (size_t)c * 128;       // 64 halfs = 128 bytes
        #pragma unroll
        for (int l = 0; l < 4; l++) {
            int r = lr + l*32;
            uint32_t d = s0 + (uint32_t)r*ROWB + (uint32_t)lg*16u;
            CPA16(d + OAH, (const char*)(Ah + (size_t)(m0 + r)*K + lg*8) + gb);
            CPA16(d + OAL, (const char*)(Al + (size_t)(m0 + r)*K + lg*8) + gb);
            CPA16(d + OBH, (const char*)(Bh + (size_t)(n0 + r)*K + lg*8) + gb);
        }
        CPA_COMMIT();
    };

    const uint32_t a_row = (uint32_t)(wm0 + (lane & 15));
    const uint32_t a_kg  = (uint32_t)(lane >> 4);
    const uint32_t b_sel = (uint32_t)(lane >> 3);
    const uint32_t b_row = (uint32_t)(wn0 + ((b_sel >> 1) << 3) + (lane & 7));
    const uint32_t b_kg  = b_sel & 1u;

    load_stage(0, 0);
    load_stage(1, 1);
    load_stage(2, 2);
    int cs = 0, ls = 3;
    for (int c = 0; c < NC; c++) {
        if (c < NC - 2)      CPA_WAIT2();
        else if (c < NC - 1) CPA_WAIT1();
        else                 CPA_WAIT0();
        __syncthreads();                   // all warps done with chunk c-1
        if (c + 3 < NC) {                  // slot ls == (c-1)&3, now free
            load_stage(ls, c + 3);
            ls = (ls + 1) & 3;
        }
        uint32_t s0 = sb + (uint32_t)cs*STAGE;
        cs = (cs + 1) & 3;

        #pragma unroll
        for (int s = 0; s < 4; s++) {      // four k16 steps per chunk
            uint32_t ah[4][4], al[4][4], bh[4][2];
            #pragma unroll
            for (int mi = 0; mi < 4; mi++) {
                uint32_t ad = s0 + (a_row + mi*16u)*ROWB + ((uint32_t)s*2u + a_kg)*16u;
                LDSM_X4(ah[mi][0], ah[mi][1], ah[mi][2], ah[mi][3], ad + OAH);
                LDSM_X4(al[mi][0], al[mi][1], al[mi][2], al[mi][3], ad + OAL);
            }
            #pragma unroll
            for (int nj = 0; nj < 4; nj += 2) {
                uint32_t bd = s0 + (b_row + (uint32_t)nj*8u)*ROWB + ((uint32_t)s*2u + b_kg)*16u;
                LDSM_X4(bh[nj][0], bh[nj][1], bh[nj+1][0], bh[nj+1][1], bd + OBH);
            }
            #pragma unroll
            for (int mi = 0; mi < 4; mi++)
                #pragma unroll
                for (int ni = 0; ni < 4; ni++) {
                    MMA_F32(acc[mi][ni], ah[mi], bh[ni]);
                    MMA_F16(a16[mi][ni], al[mi], bh[ni]);
                }
        }
    }

    float sw = 0.f;
    if (ERR) sw = 1.f / (1.f + expf(-ew[0]));
    float esum = 0.f;

    const int er = lane >> 2, ec = (lane & 3) * 2;
    #pragma unroll
    for (int mi = 0; mi < 4; mi++) {
        #pragma unroll
        for (int half = 0; half < 2; half++) {
            int m = m0 + wm0 + mi*16 + er + half*8;
            #pragma unroll
            for (int ni = 0; ni < 4; ni++) {
                int n = n0 + wn0 + ni*8 + ec;
                float2 lo = __half22float2(*(__half2*)&a16[mi][ni][half]);
                float v0 = acc[mi][ni][half*2 + 0] + lo.x * LO_INV;
                float v1 = acc[mi][ni][half*2 + 1] + lo.y * LO_INV;
                if (BIAS) { v0 += __ldg(&bias[n]); v1 += __ldg(&bias[n+1]); }
                if (GELU) {
                    v0 = 0.5f * v0 * (1.f + erff(v0 * 0.70710678118654752f));
                    v1 = 0.5f * v1 * (1.f + erff(v1 * 0.70710678118654752f));
                }
                if (ERR) {
                    float2 t = *(const float2*)(td + (size_t)m*N + n);
                    float e0 = fminf(fmaxf(v0 - t.x, -1.f), 1.f);
                    float e1 = fminf(fmaxf(v1 - t.y, -1.f), 1.f);
                    esum += e0*e0 + e1*e1;
                    v0 -= sw*e0; v1 -= sw*e1;
                }
                if (ERR || !SPLIT)
                    *(float2*)(Cf + (size_t)m*N + n) = make_float2(v0, v1);
                if (SPLIT) {
                    __half h0,l0,h1,l1;
                    split2h(v0,h0,l0); split2h(v1,h1,l1);
                    *(__half2*)(Ch + (size_t)m*N + n) = __halves2half2(h0,h1);
                    *(__half2*)(Cl + (size_t)m*N + n) = __halves2half2(l0,l1);
                }
            }
        }
    }
    if (ERR) {
        float s = block_sum<8>(esum, red);
        if (tid == 0) g_errpart[blockIdx.y * gridDim.x + blockIdx.x] = s;
    }
}

// ---------------- 32-tap complex causal FIR along S (fp16-split output) ----
__global__ void __launch_bounds__(256) conv_kernel(
    const float* __restrict__ u, __half* __restrict__ yh, __half* __restrict__ yl) {
    __shared__ float sur[63*32], sui[63*32];
    __shared__ float swr[TAPS*32], swi[TAPS*32];
    const int f0 = blockIdx.x * 32;
    const int t0 = blockIdx.y * 32;
    const int b  = blockIdx.z;
    const int tid = threadIdx.x;

    for (int i = tid; i < 63*32; i += 256) {
        int tt = i >> 5, fl = i & 31;
        int tg = t0 - 31 + tt;
        float vr = 0.f, vi = 0.f;
        if (tg >= 0) {
            size_t base = ((size_t)(b*SEQ + tg))*(2*FF) + f0 + fl;
            vr = u[base]; vi = u[base + FF];
        }
        sur[i] = vr; sui[i] = vi;
    }
    for (int i = tid; i < TAPS*32; i += 256) {
        int tt = i >> 5, fl = i & 31;
        swr[i] = g_w[tt*FF + f0 + fl];
        swi[i] = g_w[TAPS*FF + tt*FF + f0 + fl];
    }
    __syncthreads();

    const int fl = tid & 31, tr = tid >> 5;
    #pragma unroll
    for (int j = 0; j < 4; j++) {
        int tl = tr*4 + j;
        float ar = 0.f, ai = 0.f;
        #pragma unroll
        for (int t = 0; t < TAPS; t++) {
            int idx = (31 + tl - t)*32 + fl;
            float ur = sur[idx], ui = sui[idx];
            float wr = swr[t*32 + fl], wi = swi[t*32 + fl];
            ar += ur*wr - ui*wi;
            ai += ur*wi + ui*wr;
        }
        size_t ob = ((size_t)(b*SEQ + t0 + tl))*(2*FF) + f0 + fl;
        __half h, l;
        split2h(ar, h, l); yh[ob] = h;      yl[ob] = l;
        split2h(ai, h, l); yh[ob + FF] = h; yl[ob + FF] = l;
    }
}

__global__ void fin_kernel(float* __restrict__ out_scalar) {
    __shared__ float red[8];
    float s = 0.f;
    for (int i = threadIdx.x; i < 1024; i += 256) s += g_errpart[i];
    s = block_sum<8>(s, red);
    if (threadIdx.x == 0) {
        float pe = s / (float)((size_t)ROWS * DM);
        out_scalar[0] = fminf(fmaxf(pe, 0.f), 1.f);
    }
}

// ---------------- launch ----------------
extern "C" void kernel_launch(void* const* d_in, const int* in_sizes, int n_in,
                              void* d_out, int out_size) {
    const float* bu    = (const float*)d_in[0];
    const float* td    = (const float*)d_in[1];
    const float* Wspec = (const float*)d_in[2];
    const float* ldec  = (const float*)d_in[3];
    const float* freq  = (const float*)d_in[4];
    const float* Wfrom = (const float*)d_in[5];
    const float* l1g   = (const float*)d_in[6];
    const float* l1b   = (const float*)d_in[7];
    const float* W1    = (const float*)d_in[8];
    const float* b1    = (const float*)d_in[9];
    const float* W2    = (const float*)d_in[10];
    const float* b2    = (const float*)d_in[11];
    const float* l2g   = (const float*)d_in[12];
    const float* l2b   = (const float*)d_in[13];
    const float* ew    = (const float*)d_in[14];

    float* out       = (float*)d_out;
    float* corrected = out;
    float* nextpred  = out + (size_t)ROWS*DM;
    float* pe        = out + 2*(size_t)ROWS*DM;

    float *spec, *h2;
    __half *xh,*xl,*yh,*yl,*ch,*cl,*hh,*hl;
    __half *wsh,*wfh,*w1h,*w2h;
    cudaGetSymbolAddress((void**)&spec,   g_spec);
    cudaGetSymbolAddress((void**)&h2,     g_h2);
    cudaGetSymbolAddress((void**)&xh, g_xh); cudaGetSymbolAddress((void**)&xl, g_xl);
    cudaGetSymbolAddress((void**)&yh, g_yh); cudaGetSymbolAddress((void**)&yl, g_yl);
    cudaGetSymbolAddress((void**)&ch, g_ch); cudaGetSymbolAddress((void**)&cl, g_cl);
    cudaGetSymbolAddress((void**)&hh, g_hh); cudaGetSymbolAddress((void**)&hl, g_hl);
    cudaGetSymbolAddress((void**)&wsh, g_wsh);
    cudaGetSymbolAddress((void**)&wfh, g_wfh);
    cudaGetSymbolAddress((void**)&w1h, g_w1h);
    cudaGetSymbolAddress((void**)&w2h, g_w2h);

    const int SMEM_BYTES = NSTG * (int)STAGE;   // 221184
    cudaFuncSetAttribute(gemm_mma<false,false,false,false>, cudaFuncAttributeMaxDynamicSharedMemorySize, SMEM_BYTES);
    cudaFuncSetAttribute(gemm_mma<false,false,true ,true >, cudaFuncAttributeMaxDynamicSharedMemorySize, SMEM_BYTES);
    cudaFuncSetAttribute(gemm_mma<true ,true ,true ,false>, cudaFuncAttributeMaxDynamicSharedMemorySize, SMEM_BYTES);
    cudaFuncSetAttribute(gemm_mma<true ,false,false,false>, cudaFuncAttributeMaxDynamicSharedMemorySize, SMEM_BYTES);

    prep_kernel<<<1, 256>>>(ldec, freq);
    wsplit_all_kernel<<<(NW1+NW2+NW3+NW4+255)/256, 256>>>(Wspec, Wfrom, W1, W2);

    ln_kernel<true><<<ROWS, 256>>>(bu, l1g, l1b, nullptr, xh, xl);

    gemm_mma<false,false,false,false><<<dim3((2*FF)/128, ROWS/128), 256, SMEM_BYTES>>>(
        xh, xl, wsh, nullptr, spec, nullptr, nullptr, nullptr, nullptr, ROWS, 2*FF, DM);

    conv_kernel<<<dim3(FF/32, SEQ/32, BSZ), 256>>>(spec, yh, yl);

    // GEMM2 fused with error/corrected/split + per-block error sums
    gemm_mma<false,false,true,true><<<dim3(DM/128, ROWS/128), 256, SMEM_BYTES>>>(
        yh, yl, wfh, nullptr, corrected, ch, cl, td, ew, ROWS, DM, 2*FF);

    fin_kernel<<<1, 256>>>(pe);

    gemm_mma<true,true,true,false><<<dim3(DM/128, ROWS/128), 256, SMEM_BYTES>>>(
        ch, cl, w1h, b1, nullptr, hh, hl, nullptr, nullptr, ROWS, DM, DM);

    gemm_mma<true,false,false,false><<<dim3(DM/128, ROWS/128), 256, SMEM_BYTES>>>(
        hh, hl, w2h, b2, h2, nullptr, nullptr, nullptr, nullptr, ROWS, DM, DM);

    ln_kernel<false><<<ROWS, 256>>>(h2, l2g, l2b, nextpred, nullptr, nullptr);
}